// round 1
// baseline (speedup 1.0000x reference)
#include <cuda_runtime.h>
#include <cstdint>

// Problem constants
#define B_  8
#define S_  1024
#define D_  1024
#define H_  16
#define DH_ 64            // head dim
#define SCALE_ 0.125f     // 1/sqrt(64)

// Scratch buffers (allocation-free rule: __device__ globals)
__device__ float g_qkv[(size_t)B_ * S_ * 3 * D_];   // [B, S, 3D]  96 MB
__device__ float g_attn[(size_t)B_ * S_ * D_];      // [B, S, D]   32 MB (head-regrouped)

// ---------------------------------------------------------------------------
// SGEMM with bias:  C[M,N] = A[M,K] @ W[K,N] + bias[N]
// BM=BN=128, BK=16, TM=TN=8, 256 threads. M,N divisible by 128, K by 16.
// ---------------------------------------------------------------------------
__global__ __launch_bounds__(256) void sgemm_bias_kernel(
    const float* __restrict__ A, const float* __restrict__ W,
    const float* __restrict__ bias, float* __restrict__ C,
    int M, int N, int K)
{
    __shared__ float As[16][128];   // transposed A tile: As[k][m]
    __shared__ float Bs[16][128];   // Bs[k][n]

    const int tid   = threadIdx.x;
    const int mBase = blockIdx.y * 128;
    const int nBase = blockIdx.x * 128;
    const int ty = tid >> 4;   // 0..15
    const int tx = tid & 15;   // 0..15

    float acc[8][8];
    #pragma unroll
    for (int m = 0; m < 8; ++m)
        #pragma unroll
        for (int n = 0; n < 8; ++n) acc[m][n] = 0.0f;

    for (int k0 = 0; k0 < K; k0 += 16) {
        // Load A tile: 128 rows x 16 cols = 512 float4, 2 per thread
        #pragma unroll
        for (int i = 0; i < 2; ++i) {
            int idx = tid + i * 256;
            int r   = idx >> 2;      // 0..127
            int c4  = idx & 3;       // 0..3
            float4 v = *reinterpret_cast<const float4*>(
                &A[(size_t)(mBase + r) * K + k0 + c4 * 4]);
            As[c4 * 4 + 0][r] = v.x;
            As[c4 * 4 + 1][r] = v.y;
            As[c4 * 4 + 2][r] = v.z;
            As[c4 * 4 + 3][r] = v.w;
        }
        // Load B tile: 16 rows x 128 cols = 512 float4, 2 per thread
        #pragma unroll
        for (int i = 0; i < 2; ++i) {
            int idx = tid + i * 256;
            int r   = idx >> 5;      // 0..15
            int c4  = idx & 31;      // 0..31
            *reinterpret_cast<float4*>(&Bs[r][c4 * 4]) =
                *reinterpret_cast<const float4*>(
                    &W[(size_t)(k0 + r) * N + nBase + c4 * 4]);
        }
        __syncthreads();

        #pragma unroll
        for (int kk = 0; kk < 16; ++kk) {
            float ra[8], rb[8];
            *reinterpret_cast<float4*>(&ra[0]) =
                *reinterpret_cast<const float4*>(&As[kk][ty * 8 + 0]);
            *reinterpret_cast<float4*>(&ra[4]) =
                *reinterpret_cast<const float4*>(&As[kk][ty * 8 + 4]);
            *reinterpret_cast<float4*>(&rb[0]) =
                *reinterpret_cast<const float4*>(&Bs[kk][tx * 8 + 0]);
            *reinterpret_cast<float4*>(&rb[4]) =
                *reinterpret_cast<const float4*>(&Bs[kk][tx * 8 + 4]);
            #pragma unroll
            for (int m = 0; m < 8; ++m)
                #pragma unroll
                for (int n = 0; n < 8; ++n)
                    acc[m][n] += ra[m] * rb[n];
        }
        __syncthreads();
    }

    // Epilogue: add bias, vectorized store
    #pragma unroll
    for (int m = 0; m < 8; ++m) {
        int row = mBase + ty * 8 + m;
        #pragma unroll
        for (int n4 = 0; n4 < 2; ++n4) {
            int col = nBase + tx * 8 + n4 * 4;
            float4 v;
            v.x = acc[m][n4 * 4 + 0] + bias[col + 0];
            v.y = acc[m][n4 * 4 + 1] + bias[col + 1];
            v.z = acc[m][n4 * 4 + 2] + bias[col + 2];
            v.w = acc[m][n4 * 4 + 3] + bias[col + 3];
            *reinterpret_cast<float4*>(&C[(size_t)row * N + col]) = v;
        }
    }
}

// ---------------------------------------------------------------------------
// Flash-style causal attention. One thread per query row; block = 128 rows.
// grid = (S/128, B*H), block = 128 threads.
// q/k/v are slices of g_qkv [B,S,3D]: q at +0, k at +D, v at +2D (per head h:
// column offset h*64). Output written head-regrouped into g_attn[b,s,h*64+d].
// ---------------------------------------------------------------------------
__global__ __launch_bounds__(128) void attention_kernel(
    const float* __restrict__ qkv, float* __restrict__ attn)
{
    __shared__ float4 Ks4[64 * 16];   // 64 keys x 64 dims
    __shared__ float4 Vs4[64 * 16];

    const int tid = threadIdx.x;
    const int q0  = blockIdx.x * 128;
    const int bh  = blockIdx.y;
    const int b   = bh >> 4;
    const int h   = bh & 15;
    const int qi  = q0 + tid;

    const size_t rowStride = 3 * D_;
    const float* qbase = qkv + ((size_t)b * S_) * rowStride + h * DH_;
    const float* kbase = qbase + D_;
    const float* vbase = qbase + 2 * D_;

    // Load this thread's q row into registers (16 float4 = 64 floats)
    float4 q[16];
    {
        const float4* qp = reinterpret_cast<const float4*>(qbase + (size_t)qi * rowStride);
        #pragma unroll
        for (int d = 0; d < 16; ++d) q[d] = qp[d];
    }

    float4 o[16];
    #pragma unroll
    for (int d = 0; d < 16; ++d) o[d] = make_float4(0.f, 0.f, 0.f, 0.f);
    float mrun = -1e30f;
    float lrun = 0.0f;

    const int ktNum = (q0 + 128 + 63) / 64;   // k-tiles covering keys 0..q0+127
    for (int kt = 0; kt < ktNum; ++kt) {
        const int ks = kt * 64;

        // Cooperative load of K and V tiles (64 rows x 16 float4 each)
        #pragma unroll
        for (int i = 0; i < 8; ++i) {
            int idx = tid + i * 128;
            int r   = idx >> 4;     // 0..63
            int c4  = idx & 15;     // 0..15
            Ks4[r * 16 + c4] = *reinterpret_cast<const float4*>(
                kbase + (size_t)(ks + r) * rowStride + c4 * 4);
            Vs4[r * 16 + c4] = *reinterpret_cast<const float4*>(
                vbase + (size_t)(ks + r) * rowStride + c4 * 4);
        }
        __syncthreads();

        int jmax = qi - ks + 1;           // causal: keys <= qi
        if (jmax > 64) jmax = 64;

        for (int j = 0; j < jmax; ++j) {
            // dot(q, K[j]) with 4 partial accumulators (break dep chain)
            const float4* kr = &Ks4[j * 16];
            float s0 = 0.f, s1 = 0.f, s2 = 0.f, s3 = 0.f;
            #pragma unroll
            for (int d = 0; d < 16; d += 4) {
                float4 a0 = q[d + 0], k0v = kr[d + 0];
                float4 a1 = q[d + 1], k1v = kr[d + 1];
                float4 a2 = q[d + 2], k2v = kr[d + 2];
                float4 a3 = q[d + 3], k3v = kr[d + 3];
                s0 += a0.x * k0v.x + a0.y * k0v.y + a0.z * k0v.z + a0.w * k0v.w;
                s1 += a1.x * k1v.x + a1.y * k1v.y + a1.z * k1v.z + a1.w * k1v.w;
                s2 += a2.x * k2v.x + a2.y * k2v.y + a2.z * k2v.z + a2.w * k2v.w;
                s3 += a3.x * k3v.x + a3.y * k3v.y + a3.z * k3v.z + a3.w * k3v.w;
            }
            float s = ((s0 + s1) + (s2 + s3)) * SCALE_;

            float p;
            if (s > mrun) {
                float corr = __expf(mrun - s);
                mrun = s;
                lrun *= corr;
                p = 1.0f;
                #pragma unroll
                for (int d = 0; d < 16; ++d) {
                    o[d].x *= corr; o[d].y *= corr;
                    o[d].z *= corr; o[d].w *= corr;
                }
            } else {
                p = __expf(s - mrun);
            }
            lrun += p;

            const float4* vr = &Vs4[j * 16];
            #pragma unroll
            for (int d = 0; d < 16; ++d) {
                float4 v = vr[d];
                o[d].x += p * v.x; o[d].y += p * v.y;
                o[d].z += p * v.z; o[d].w += p * v.w;
            }
        }
        __syncthreads();
    }

    // Normalize and write head-regrouped output: attn[b, qi, h*64 + d]
    const float inv = 1.0f / lrun;
    float4* outp = reinterpret_cast<float4*>(
        attn + ((size_t)b * S_ + qi) * D_ + h * DH_);
    #pragma unroll
    for (int d = 0; d < 16; ++d) {
        float4 v = o[d];
        v.x *= inv; v.y *= inv; v.z *= inv; v.w *= inv;
        outp[d] = v;
    }
}

// ---------------------------------------------------------------------------
// Launch: QKV GEMM -> attention -> output GEMM
// Inputs (metadata order): x, W_qkv, b_qkv, W_out, b_out. Output fp32 [B,S,D].
// ---------------------------------------------------------------------------
extern "C" void kernel_launch(void* const* d_in, const int* in_sizes, int n_in,
                              void* d_out, int out_size)
{
    (void)in_sizes; (void)n_in; (void)out_size;
    const float* x     = (const float*)d_in[0];
    const float* W_qkv = (const float*)d_in[1];
    const float* b_qkv = (const float*)d_in[2];
    const float* W_out = (const float*)d_in[3];
    const float* b_out = (const float*)d_in[4];
    float* out = (float*)d_out;

    float* qkv  = nullptr;
    float* attn = nullptr;
    cudaGetSymbolAddress((void**)&qkv,  g_qkv);
    cudaGetSymbolAddress((void**)&attn, g_attn);

    // 1) QKV projection: [8192,1024] @ [1024,3072] + b  -> g_qkv
    {
        dim3 grid(3 * D_ / 128, (B_ * S_) / 128);   // (24, 64)
        sgemm_bias_kernel<<<grid, 256>>>(x, W_qkv, b_qkv, qkv,
                                         B_ * S_, 3 * D_, D_);
    }

    // 2) Causal flash attention -> g_attn (head-regrouped [B,S,D])
    {
        dim3 grid(S_ / 128, B_ * H_);               // (8, 128)
        attention_kernel<<<grid, 128>>>(qkv, attn);
    }

    // 3) Output projection: [8192,1024] @ [1024,1024] + b -> d_out
    {
        dim3 grid(D_ / 128, (B_ * S_) / 128);       // (8, 64)
        sgemm_bias_kernel<<<grid, 256>>>(attn, W_out, b_out, out,
                                         B_ * S_, D_, D_);
    }
}

// round 2
// speedup vs baseline: 1.8250x; 1.8250x over previous
#include <cuda_runtime.h>
#include <cstdint>

// Problem constants
#define B_  8
#define S_  1024
#define D_  1024
#define H_  16
#define DH_ 64
#define SCALE_ 0.125f     // 1/sqrt(64)

// Scratch buffers (allocation-free rule: __device__ globals)
__device__ float g_qkv[(size_t)B_ * S_ * 3 * D_];   // [B, S, 3D]
__device__ float g_attn[(size_t)B_ * S_ * D_];      // [B, S, D] head-regrouped

// ---------------------------------------------------------------------------
// TF32 tensor-core helpers
// ---------------------------------------------------------------------------
__device__ __forceinline__ uint32_t f2tf32(float f) {
    uint32_t r;
    asm("cvt.rna.tf32.f32 %0, %1;" : "=r"(r) : "f"(f));
    return r;
}

__device__ __forceinline__ void mma_tf32(
    float& d0, float& d1, float& d2, float& d3,
    uint32_t a0, uint32_t a1, uint32_t a2, uint32_t a3,
    uint32_t b0, uint32_t b1)
{
    asm volatile(
        "mma.sync.aligned.m16n8k8.row.col.f32.tf32.tf32.f32 "
        "{%0,%1,%2,%3}, {%4,%5,%6,%7}, {%8,%9}, {%0,%1,%2,%3};"
        : "+f"(d0), "+f"(d1), "+f"(d2), "+f"(d3)
        : "r"(a0), "r"(a1), "r"(a2), "r"(a3), "r"(b0), "r"(b1));
}

__device__ __forceinline__ void cp_async16(uint32_t s, const void* g) {
    asm volatile("cp.async.cg.shared.global [%0], [%1], 16;" :: "r"(s), "l"(g));
}
__device__ __forceinline__ uint32_t smem_u32(const void* p) {
    return (uint32_t)__cvta_generic_to_shared(p);
}

// ---------------------------------------------------------------------------
// TF32 tensor-core GEMM + bias:  C[M,N] = A[M,K] @ W[K,N] + bias[N]
// BM=BN=128, BK=32. 256 threads = 8 warps (2m x 4n), warp tile 64x32.
// mma.sync m16n8k8 tf32, fp32 accumulate. cp.async double buffer.
// Shared layout (per buffer): As[128][36] row-major, Bs[32][136] row-major.
// Strides chosen conflict-free for the fragment gather patterns.
// ---------------------------------------------------------------------------
#define AS_STRIDE 36
#define BS_STRIDE 136
#define A_TILE_F (128 * AS_STRIDE)          // 4608 floats
#define B_TILE_F (32 * BS_STRIDE)           // 4352 floats
#define BUF_F    (A_TILE_F + B_TILE_F)      // 8960 floats
#define SMEM_BYTES (2 * BUF_F * 4)          // 71680 bytes

__global__ __launch_bounds__(256, 2) void gemm_tf32_kernel(
    const float* __restrict__ A, const float* __restrict__ W,
    const float* __restrict__ bias, float* __restrict__ C,
    int M, int N, int K)
{
    extern __shared__ float sm[];

    const int tid  = threadIdx.x;
    const int lane = tid & 31;
    const int warp = tid >> 5;
    const int wm   = warp & 1;       // 0..1
    const int wn   = warp >> 1;      // 0..3
    const int mBase = blockIdx.y * 128;
    const int nBase = blockIdx.x * 128;
    const int g  = lane >> 2;        // 0..7
    const int t  = lane & 3;         // 0..3

    float acc[4][4][4];              // [mt][nt][frag]
    #pragma unroll
    for (int mt = 0; mt < 4; ++mt)
        #pragma unroll
        for (int nt = 0; nt < 4; ++nt)
            #pragma unroll
            for (int f = 0; f < 4; ++f) acc[mt][nt][f] = 0.0f;

    // ---- tile loader (cp.async, one commit group per tile) ----
    auto loadTile = [&](int buf, int k0) {
        float* As = sm + buf * BUF_F;
        float* Bs = As + A_TILE_F;
        #pragma unroll
        for (int j = 0; j < 4; ++j) {          // A: 128x32 = 1024 float4
            int idx = tid + j * 256;
            int r = idx >> 3, c4 = idx & 7;
            cp_async16(smem_u32(As + r * AS_STRIDE + c4 * 4),
                       &A[(size_t)(mBase + r) * K + k0 + c4 * 4]);
        }
        #pragma unroll
        for (int j = 0; j < 4; ++j) {          // B: 32x128 = 1024 float4
            int idx = tid + j * 256;
            int r = idx >> 5, c4 = idx & 31;
            cp_async16(smem_u32(Bs + r * BS_STRIDE + c4 * 4),
                       &W[(size_t)(k0 + r) * N + nBase + c4 * 4]);
        }
        asm volatile("cp.async.commit_group;");
    };

    const int nIter = K / 32;
    loadTile(0, 0);

    for (int it = 0; it < nIter; ++it) {
        if (it + 1 < nIter) {
            loadTile((it + 1) & 1, (it + 1) * 32);
            asm volatile("cp.async.wait_group 1;");
        } else {
            asm volatile("cp.async.wait_group 0;");
        }
        __syncthreads();

        const float* As = sm + (it & 1) * BUF_F;
        const float* Bs = As + A_TILE_F;

        #pragma unroll
        for (int kk = 0; kk < 4; ++kk) {
            const int kc = kk * 8;

            uint32_t af[4][4];
            #pragma unroll
            for (int mt = 0; mt < 4; ++mt) {
                int r = wm * 64 + mt * 16 + g;
                af[mt][0] = f2tf32(As[(r    ) * AS_STRIDE + kc + t    ]);
                af[mt][1] = f2tf32(As[(r + 8) * AS_STRIDE + kc + t    ]);
                af[mt][2] = f2tf32(As[(r    ) * AS_STRIDE + kc + t + 4]);
                af[mt][3] = f2tf32(As[(r + 8) * AS_STRIDE + kc + t + 4]);
            }
            uint32_t bf[4][2];
            #pragma unroll
            for (int nt = 0; nt < 4; ++nt) {
                int n = wn * 32 + nt * 8 + g;
                bf[nt][0] = f2tf32(Bs[(kc + t    ) * BS_STRIDE + n]);
                bf[nt][1] = f2tf32(Bs[(kc + t + 4) * BS_STRIDE + n]);
            }
            #pragma unroll
            for (int mt = 0; mt < 4; ++mt)
                #pragma unroll
                for (int nt = 0; nt < 4; ++nt)
                    mma_tf32(acc[mt][nt][0], acc[mt][nt][1],
                             acc[mt][nt][2], acc[mt][nt][3],
                             af[mt][0], af[mt][1], af[mt][2], af[mt][3],
                             bf[nt][0], bf[nt][1]);
        }
        __syncthreads();
    }

    // ---- epilogue: bias add, float2 stores ----
    #pragma unroll
    for (int mt = 0; mt < 4; ++mt) {
        int r0 = mBase + wm * 64 + mt * 16 + g;
        int r1 = r0 + 8;
        #pragma unroll
        for (int nt = 0; nt < 4; ++nt) {
            int col = nBase + wn * 32 + nt * 8 + t * 2;
            float2 bv = *reinterpret_cast<const float2*>(&bias[col]);
            float2 v0, v1;
            v0.x = acc[mt][nt][0] + bv.x;
            v0.y = acc[mt][nt][1] + bv.y;
            v1.x = acc[mt][nt][2] + bv.x;
            v1.y = acc[mt][nt][3] + bv.y;
            *reinterpret_cast<float2*>(&C[(size_t)r0 * N + col]) = v0;
            *reinterpret_cast<float2*>(&C[(size_t)r1 * N + col]) = v1;
        }
    }
}

// ---------------------------------------------------------------------------
// Flash-style causal attention (unchanged from R1).
// One thread per query row; block = 128 rows. grid = (S/128, B*H).
// ---------------------------------------------------------------------------
__global__ __launch_bounds__(128) void attention_kernel(
    const float* __restrict__ qkv, float* __restrict__ attn)
{
    __shared__ float4 Ks4[64 * 16];
    __shared__ float4 Vs4[64 * 16];

    const int tid = threadIdx.x;
    const int q0  = blockIdx.x * 128;
    const int bh  = blockIdx.y;
    const int b   = bh >> 4;
    const int h   = bh & 15;
    const int qi  = q0 + tid;

    const size_t rowStride = 3 * D_;
    const float* qbase = qkv + ((size_t)b * S_) * rowStride + h * DH_;
    const float* kbase = qbase + D_;
    const float* vbase = qbase + 2 * D_;

    float4 q[16];
    {
        const float4* qp = reinterpret_cast<const float4*>(qbase + (size_t)qi * rowStride);
        #pragma unroll
        for (int d = 0; d < 16; ++d) q[d] = qp[d];
    }

    float4 o[16];
    #pragma unroll
    for (int d = 0; d < 16; ++d) o[d] = make_float4(0.f, 0.f, 0.f, 0.f);
    float mrun = -1e30f;
    float lrun = 0.0f;

    const int ktNum = (q0 + 128 + 63) / 64;
    for (int kt = 0; kt < ktNum; ++kt) {
        const int ks = kt * 64;

        #pragma unroll
        for (int i = 0; i < 8; ++i) {
            int idx = tid + i * 128;
            int r   = idx >> 4;
            int c4  = idx & 15;
            Ks4[r * 16 + c4] = *reinterpret_cast<const float4*>(
                kbase + (size_t)(ks + r) * rowStride + c4 * 4);
            Vs4[r * 16 + c4] = *reinterpret_cast<const float4*>(
                vbase + (size_t)(ks + r) * rowStride + c4 * 4);
        }
        __syncthreads();

        int jmax = qi - ks + 1;
        if (jmax > 64) jmax = 64;

        for (int j = 0; j < jmax; ++j) {
            const float4* kr = &Ks4[j * 16];
            float s0 = 0.f, s1 = 0.f, s2 = 0.f, s3 = 0.f;
            #pragma unroll
            for (int d = 0; d < 16; d += 4) {
                float4 a0 = q[d + 0], k0v = kr[d + 0];
                float4 a1 = q[d + 1], k1v = kr[d + 1];
                float4 a2 = q[d + 2], k2v = kr[d + 2];
                float4 a3 = q[d + 3], k3v = kr[d + 3];
                s0 += a0.x * k0v.x + a0.y * k0v.y + a0.z * k0v.z + a0.w * k0v.w;
                s1 += a1.x * k1v.x + a1.y * k1v.y + a1.z * k1v.z + a1.w * k1v.w;
                s2 += a2.x * k2v.x + a2.y * k2v.y + a2.z * k2v.z + a2.w * k2v.w;
                s3 += a3.x * k3v.x + a3.y * k3v.y + a3.z * k3v.z + a3.w * k3v.w;
            }
            float s = ((s0 + s1) + (s2 + s3)) * SCALE_;

            float p;
            if (s > mrun) {
                float corr = __expf(mrun - s);
                mrun = s;
                lrun *= corr;
                p = 1.0f;
                #pragma unroll
                for (int d = 0; d < 16; ++d) {
                    o[d].x *= corr; o[d].y *= corr;
                    o[d].z *= corr; o[d].w *= corr;
                }
            } else {
                p = __expf(s - mrun);
            }
            lrun += p;

            const float4* vr = &Vs4[j * 16];
            #pragma unroll
            for (int d = 0; d < 16; ++d) {
                float4 v = vr[d];
                o[d].x += p * v.x; o[d].y += p * v.y;
                o[d].z += p * v.z; o[d].w += p * v.w;
            }
        }
        __syncthreads();
    }

    const float inv = 1.0f / lrun;
    float4* outp = reinterpret_cast<float4*>(
        attn + ((size_t)b * S_ + qi) * D_ + h * DH_);
    #pragma unroll
    for (int d = 0; d < 16; ++d) {
        float4 v = o[d];
        v.x *= inv; v.y *= inv; v.z *= inv; v.w *= inv;
        outp[d] = v;
    }
}

// ---------------------------------------------------------------------------
// Launch
// ---------------------------------------------------------------------------
extern "C" void kernel_launch(void* const* d_in, const int* in_sizes, int n_in,
                              void* d_out, int out_size)
{
    (void)in_sizes; (void)n_in; (void)out_size;
    const float* x     = (const float*)d_in[0];
    const float* W_qkv = (const float*)d_in[1];
    const float* b_qkv = (const float*)d_in[2];
    const float* W_out = (const float*)d_in[3];
    const float* b_out = (const float*)d_in[4];
    float* out = (float*)d_out;

    float* qkv  = nullptr;
    float* attn = nullptr;
    cudaGetSymbolAddress((void**)&qkv,  g_qkv);
    cudaGetSymbolAddress((void**)&attn, g_attn);

    cudaFuncSetAttribute(gemm_tf32_kernel,
                         cudaFuncAttributeMaxDynamicSharedMemorySize, SMEM_BYTES);

    // 1) QKV projection: [8192,1024] @ [1024,3072] + b  -> g_qkv
    {
        dim3 grid(3 * D_ / 128, (B_ * S_) / 128);   // (24, 64)
        gemm_tf32_kernel<<<grid, 256, SMEM_BYTES>>>(x, W_qkv, b_qkv, qkv,
                                                    B_ * S_, 3 * D_, D_);
    }

    // 2) Causal flash attention -> g_attn (head-regrouped [B,S,D])
    {
        dim3 grid(S_ / 128, B_ * H_);               // (8, 128)
        attention_kernel<<<grid, 128>>>(qkv, attn);
    }

    // 3) Output projection: [8192,1024] @ [1024,1024] + b -> d_out
    {
        dim3 grid(D_ / 128, (B_ * S_) / 128);       // (8, 64)
        gemm_tf32_kernel<<<grid, 256, SMEM_BYTES>>>(attn, W_out, b_out, out,
                                                    B_ * S_, D_, D_);
    }
}

// round 3
// speedup vs baseline: 3.6284x; 1.9881x over previous
#include <cuda_runtime.h>
#include <cstdint>

// Problem constants
#define B_  8
#define S_  1024
#define D_  1024
#define H_  16
#define DH_ 64

// Scratch buffers (allocation-free rule: __device__ globals)
__device__ float g_qkv[(size_t)B_ * S_ * 3 * D_];   // [B, S, 3D]
__device__ float g_attn[(size_t)B_ * S_ * D_];      // [B, S, D] head-regrouped

// ---------------------------------------------------------------------------
// TF32 tensor-core helpers
// ---------------------------------------------------------------------------
__device__ __forceinline__ uint32_t f2tf32(float f) {
    uint32_t r;
    asm("cvt.rna.tf32.f32 %0, %1;" : "=r"(r) : "f"(f));
    return r;
}

__device__ __forceinline__ void mma_tf32(
    float& d0, float& d1, float& d2, float& d3,
    uint32_t a0, uint32_t a1, uint32_t a2, uint32_t a3,
    uint32_t b0, uint32_t b1)
{
    asm volatile(
        "mma.sync.aligned.m16n8k8.row.col.f32.tf32.tf32.f32 "
        "{%0,%1,%2,%3}, {%4,%5,%6,%7}, {%8,%9}, {%0,%1,%2,%3};"
        : "+f"(d0), "+f"(d1), "+f"(d2), "+f"(d3)
        : "r"(a0), "r"(a1), "r"(a2), "r"(a3), "r"(b0), "r"(b1));
}

__device__ __forceinline__ void cp_async16(uint32_t s, const void* g) {
    asm volatile("cp.async.cg.shared.global [%0], [%1], 16;" :: "r"(s), "l"(g));
}
__device__ __forceinline__ uint32_t smem_u32(const void* p) {
    return (uint32_t)__cvta_generic_to_shared(p);
}

// ---------------------------------------------------------------------------
// TF32 tensor-core GEMM + bias (unchanged from R2)
// ---------------------------------------------------------------------------
#define AS_STRIDE 36
#define BS_STRIDE 136
#define A_TILE_F (128 * AS_STRIDE)
#define B_TILE_F (32 * BS_STRIDE)
#define BUF_F    (A_TILE_F + B_TILE_F)
#define SMEM_BYTES (2 * BUF_F * 4)

__global__ __launch_bounds__(256, 2) void gemm_tf32_kernel(
    const float* __restrict__ A, const float* __restrict__ W,
    const float* __restrict__ bias, float* __restrict__ C,
    int M, int N, int K)
{
    extern __shared__ float sm[];

    const int tid  = threadIdx.x;
    const int lane = tid & 31;
    const int warp = tid >> 5;
    const int wm   = warp & 1;
    const int wn   = warp >> 1;
    const int mBase = blockIdx.y * 128;
    const int nBase = blockIdx.x * 128;
    const int g  = lane >> 2;
    const int t  = lane & 3;

    float acc[4][4][4];
    #pragma unroll
    for (int mt = 0; mt < 4; ++mt)
        #pragma unroll
        for (int nt = 0; nt < 4; ++nt)
            #pragma unroll
            for (int f = 0; f < 4; ++f) acc[mt][nt][f] = 0.0f;

    auto loadTile = [&](int buf, int k0) {
        float* As = sm + buf * BUF_F;
        float* Bs = As + A_TILE_F;
        #pragma unroll
        for (int j = 0; j < 4; ++j) {
            int idx = tid + j * 256;
            int r = idx >> 3, c4 = idx & 7;
            cp_async16(smem_u32(As + r * AS_STRIDE + c4 * 4),
                       &A[(size_t)(mBase + r) * K + k0 + c4 * 4]);
        }
        #pragma unroll
        for (int j = 0; j < 4; ++j) {
            int idx = tid + j * 256;
            int r = idx >> 5, c4 = idx & 31;
            cp_async16(smem_u32(Bs + r * BS_STRIDE + c4 * 4),
                       &W[(size_t)(k0 + r) * N + nBase + c4 * 4]);
        }
        asm volatile("cp.async.commit_group;");
    };

    const int nIter = K / 32;
    loadTile(0, 0);

    for (int it = 0; it < nIter; ++it) {
        if (it + 1 < nIter) {
            loadTile((it + 1) & 1, (it + 1) * 32);
            asm volatile("cp.async.wait_group 1;");
        } else {
            asm volatile("cp.async.wait_group 0;");
        }
        __syncthreads();

        const float* As = sm + (it & 1) * BUF_F;
        const float* Bs = As + A_TILE_F;

        #pragma unroll
        for (int kk = 0; kk < 4; ++kk) {
            const int kc = kk * 8;

            uint32_t af[4][4];
            #pragma unroll
            for (int mt = 0; mt < 4; ++mt) {
                int r = wm * 64 + mt * 16 + g;
                af[mt][0] = f2tf32(As[(r    ) * AS_STRIDE + kc + t    ]);
                af[mt][1] = f2tf32(As[(r + 8) * AS_STRIDE + kc + t    ]);
                af[mt][2] = f2tf32(As[(r    ) * AS_STRIDE + kc + t + 4]);
                af[mt][3] = f2tf32(As[(r + 8) * AS_STRIDE + kc + t + 4]);
            }
            uint32_t bf[4][2];
            #pragma unroll
            for (int nt = 0; nt < 4; ++nt) {
                int n = wn * 32 + nt * 8 + g;
                bf[nt][0] = f2tf32(Bs[(kc + t    ) * BS_STRIDE + n]);
                bf[nt][1] = f2tf32(Bs[(kc + t + 4) * BS_STRIDE + n]);
            }
            #pragma unroll
            for (int mt = 0; mt < 4; ++mt)
                #pragma unroll
                for (int nt = 0; nt < 4; ++nt)
                    mma_tf32(acc[mt][nt][0], acc[mt][nt][1],
                             acc[mt][nt][2], acc[mt][nt][3],
                             af[mt][0], af[mt][1], af[mt][2], af[mt][3],
                             bf[nt][0], bf[nt][1]);
        }
        __syncthreads();
    }

    #pragma unroll
    for (int mt = 0; mt < 4; ++mt) {
        int r0 = mBase + wm * 64 + mt * 16 + g;
        int r1 = r0 + 8;
        #pragma unroll
        for (int nt = 0; nt < 4; ++nt) {
            int col = nBase + wn * 32 + nt * 8 + t * 2;
            float2 bv = *reinterpret_cast<const float2*>(&bias[col]);
            float2 v0, v1;
            v0.x = acc[mt][nt][0] + bv.x;
            v0.y = acc[mt][nt][1] + bv.y;
            v1.x = acc[mt][nt][2] + bv.x;
            v1.y = acc[mt][nt][3] + bv.y;
            *reinterpret_cast<float2*>(&C[(size_t)r0 * N + col]) = v0;
            *reinterpret_cast<float2*>(&C[(size_t)r1 * N + col]) = v1;
        }
    }
}

// ---------------------------------------------------------------------------
// Tensor-core FlashAttention (tf32, causal).
// Block = 128 query rows of one (b,h); 256 threads = 8 warps, 16 rows/warp.
// Key tiles of 64. Q scaled by 1/8 (exact) and held as register fragments.
// Q smem region is reused for the P tile between the two MMAs.
// grid = (8, B*H).
// ---------------------------------------------------------------------------
#define QP_STRIDE 68
#define K_STRIDE  68
#define V_STRIDE  72
#define QP_F (128 * QP_STRIDE)          // 8704 floats
#define K_F  (64 * K_STRIDE)            // 4352
#define V_F  (64 * V_STRIDE)            // 4608
#define ATT_SMEM_BYTES ((QP_F + K_F + V_F) * 4)   // 70656 B

__global__ __launch_bounds__(256, 2) void attention_tc_kernel(
    const float* __restrict__ qkv, float* __restrict__ attn)
{
    extern __shared__ float sm[];
    float* QP = sm;
    float* Ks = sm + QP_F;
    float* Vs = Ks + K_F;
    uint32_t* QPu = reinterpret_cast<uint32_t*>(QP);
    const uint32_t* Vsu = reinterpret_cast<const uint32_t*>(Vs);

    const int tid  = threadIdx.x;
    const int lane = tid & 31;
    const int warp = tid >> 5;          // 0..7
    const int g = lane >> 2;            // 0..7
    const int t = lane & 3;             // 0..3
    const int q0 = (7 - blockIdx.x) * 128;   // heavy tiles first
    const int bh = blockIdx.y;
    const int b  = bh >> 4;
    const int h  = bh & 15;

    const float* qbase = qkv + (size_t)b * S_ * 3072 + h * DH_;
    const float* kbase = qbase + D_;
    const float* vbase = qbase + 2 * D_;

    // ---- Load Q tile (scaled by 1/8 = exact) into smem ----
    #pragma unroll
    for (int i = 0; i < 8; ++i) {
        int idx = tid + i * 256;
        int r = idx >> 4, c4 = idx & 15;
        float4 v = *reinterpret_cast<const float4*>(
            qbase + (size_t)(q0 + r) * 3072 + c4 * 4);
        v.x *= 0.125f; v.y *= 0.125f; v.z *= 0.125f; v.w *= 0.125f;
        *reinterpret_cast<float4*>(QP + r * QP_STRIDE + c4 * 4) = v;
    }
    __syncthreads();

    // ---- Build Q fragments in registers ----
    const int rowA = warp * 16 + g;     // local query row of this lane (and +8)
    uint32_t qf[8][4];
    #pragma unroll
    for (int kk = 0; kk < 8; ++kk) {
        int c = kk * 8;
        qf[kk][0] = f2tf32(QP[(rowA    ) * QP_STRIDE + c + t    ]);
        qf[kk][1] = f2tf32(QP[(rowA + 8) * QP_STRIDE + c + t    ]);
        qf[kk][2] = f2tf32(QP[(rowA    ) * QP_STRIDE + c + t + 4]);
        qf[kk][3] = f2tf32(QP[(rowA + 8) * QP_STRIDE + c + t + 4]);
    }

    float of[8][4];
    #pragma unroll
    for (int nt = 0; nt < 8; ++nt)
        #pragma unroll
        for (int f = 0; f < 4; ++f) of[nt][f] = 0.0f;
    float m0 = -1e30f, m1 = -1e30f, l0 = 0.0f, l1 = 0.0f;

    const int nTiles = q0 / 64 + 2;
    for (int kt = 0; kt < nTiles; ++kt) {
        const int ks = kt * 64;
        __syncthreads();   // previous iteration's Vs/QPu reads done

        // ---- Load K,V tiles ----
        #pragma unroll
        for (int i = 0; i < 4; ++i) {
            int idx = tid + i * 256;
            int r = idx >> 4, c4 = idx & 15;
            *reinterpret_cast<float4*>(Ks + r * K_STRIDE + c4 * 4) =
                *reinterpret_cast<const float4*>(
                    kbase + (size_t)(ks + r) * 3072 + c4 * 4);
            *reinterpret_cast<float4*>(Vs + r * V_STRIDE + c4 * 4) =
                *reinterpret_cast<const float4*>(
                    vbase + (size_t)(ks + r) * 3072 + c4 * 4);
        }
        __syncthreads();

        // ---- S = (Q/8) @ K^T ----
        float sv[8][4];
        #pragma unroll
        for (int nt = 0; nt < 8; ++nt) {
            sv[nt][0] = sv[nt][1] = sv[nt][2] = sv[nt][3] = 0.0f;
            #pragma unroll
            for (int kk = 0; kk < 8; ++kk) {
                uint32_t b0 = f2tf32(Ks[(nt * 8 + g) * K_STRIDE + kk * 8 + t    ]);
                uint32_t b1 = f2tf32(Ks[(nt * 8 + g) * K_STRIDE + kk * 8 + t + 4]);
                mma_tf32(sv[nt][0], sv[nt][1], sv[nt][2], sv[nt][3],
                         qf[kk][0], qf[kk][1], qf[kk][2], qf[kk][3], b0, b1);
            }
        }

        // ---- Causal mask (only diagonal tiles) ----
        if (ks >= q0) {
            int r0 = q0 + rowA, r1 = r0 + 8;
            #pragma unroll
            for (int nt = 0; nt < 8; ++nt) {
                int c0 = ks + nt * 8 + 2 * t, c1 = c0 + 1;
                if (c0 > r0) sv[nt][0] = -1e30f;
                if (c1 > r0) sv[nt][1] = -1e30f;
                if (c0 > r1) sv[nt][2] = -1e30f;
                if (c1 > r1) sv[nt][3] = -1e30f;
            }
        }

        // ---- Online softmax (rows r0 -> m0/l0, r1 -> m1/l1) ----
        float rx0 = -1e30f, rx1 = -1e30f;
        #pragma unroll
        for (int nt = 0; nt < 8; ++nt) {
            rx0 = fmaxf(rx0, fmaxf(sv[nt][0], sv[nt][1]));
            rx1 = fmaxf(rx1, fmaxf(sv[nt][2], sv[nt][3]));
        }
        rx0 = fmaxf(rx0, __shfl_xor_sync(0xffffffffu, rx0, 1));
        rx0 = fmaxf(rx0, __shfl_xor_sync(0xffffffffu, rx0, 2));
        rx1 = fmaxf(rx1, __shfl_xor_sync(0xffffffffu, rx1, 1));
        rx1 = fmaxf(rx1, __shfl_xor_sync(0xffffffffu, rx1, 2));

        float mn0 = fmaxf(m0, rx0), mn1 = fmaxf(m1, rx1);
        float corr0 = __expf(m0 - mn0), corr1 = __expf(m1 - mn1);
        m0 = mn0; m1 = mn1;

        float ps0 = 0.0f, ps1 = 0.0f;
        #pragma unroll
        for (int nt = 0; nt < 8; ++nt) {
            float p0 = __expf(sv[nt][0] - m0);
            float p1 = __expf(sv[nt][1] - m0);
            float p2 = __expf(sv[nt][2] - m1);
            float p3 = __expf(sv[nt][3] - m1);
            ps0 += p0 + p1;
            ps1 += p2 + p3;
            uint2 w0; w0.x = f2tf32(p0); w0.y = f2tf32(p1);
            uint2 w1; w1.x = f2tf32(p2); w1.y = f2tf32(p3);
            *reinterpret_cast<uint2*>(QPu + (rowA    ) * QP_STRIDE + nt * 8 + 2 * t) = w0;
            *reinterpret_cast<uint2*>(QPu + (rowA + 8) * QP_STRIDE + nt * 8 + 2 * t) = w1;
        }
        ps0 += __shfl_xor_sync(0xffffffffu, ps0, 1);
        ps0 += __shfl_xor_sync(0xffffffffu, ps0, 2);
        ps1 += __shfl_xor_sync(0xffffffffu, ps1, 1);
        ps1 += __shfl_xor_sync(0xffffffffu, ps1, 2);
        l0 = l0 * corr0 + ps0;
        l1 = l1 * corr1 + ps1;

        #pragma unroll
        for (int nt = 0; nt < 8; ++nt) {
            of[nt][0] *= corr0; of[nt][1] *= corr0;
            of[nt][2] *= corr1; of[nt][3] *= corr1;
        }
        __syncwarp();   // P rows are warp-private: order STS before LDS

        // ---- O += P @ V ----
        #pragma unroll
        for (int kk = 0; kk < 8; ++kk) {
            uint32_t a0 = QPu[(rowA    ) * QP_STRIDE + kk * 8 + t    ];
            uint32_t a1 = QPu[(rowA + 8) * QP_STRIDE + kk * 8 + t    ];
            uint32_t a2 = QPu[(rowA    ) * QP_STRIDE + kk * 8 + t + 4];
            uint32_t a3 = QPu[(rowA + 8) * QP_STRIDE + kk * 8 + t + 4];
            #pragma unroll
            for (int nt = 0; nt < 8; ++nt) {
                uint32_t b0 = f2tf32(Vs[(kk * 8 + t    ) * V_STRIDE + nt * 8 + g]);
                uint32_t b1 = f2tf32(Vs[(kk * 8 + t + 4) * V_STRIDE + nt * 8 + g]);
                mma_tf32(of[nt][0], of[nt][1], of[nt][2], of[nt][3],
                         a0, a1, a2, a3, b0, b1);
            }
        }
    }

    // ---- Normalize and store head-regrouped output ----
    const float inv0 = 1.0f / l0;
    const float inv1 = 1.0f / l1;
    const int r0 = q0 + rowA;
    float* obase = attn + ((size_t)b * S_ + r0) * D_ + h * DH_;
    #pragma unroll
    for (int nt = 0; nt < 8; ++nt) {
        int col = nt * 8 + 2 * t;
        float2 v0, v1;
        v0.x = of[nt][0] * inv0; v0.y = of[nt][1] * inv0;
        v1.x = of[nt][2] * inv1; v1.y = of[nt][3] * inv1;
        *reinterpret_cast<float2*>(obase + col) = v0;
        *reinterpret_cast<float2*>(obase + 8 * (size_t)D_ + col) = v1;
    }
}

// ---------------------------------------------------------------------------
// Launch
// ---------------------------------------------------------------------------
extern "C" void kernel_launch(void* const* d_in, const int* in_sizes, int n_in,
                              void* d_out, int out_size)
{
    (void)in_sizes; (void)n_in; (void)out_size;
    const float* x     = (const float*)d_in[0];
    const float* W_qkv = (const float*)d_in[1];
    const float* b_qkv = (const float*)d_in[2];
    const float* W_out = (const float*)d_in[3];
    const float* b_out = (const float*)d_in[4];
    float* out = (float*)d_out;

    float* qkv  = nullptr;
    float* attn = nullptr;
    cudaGetSymbolAddress((void**)&qkv,  g_qkv);
    cudaGetSymbolAddress((void**)&attn, g_attn);

    cudaFuncSetAttribute(gemm_tf32_kernel,
                         cudaFuncAttributeMaxDynamicSharedMemorySize, SMEM_BYTES);
    cudaFuncSetAttribute(attention_tc_kernel,
                         cudaFuncAttributeMaxDynamicSharedMemorySize, ATT_SMEM_BYTES);

    // 1) QKV projection: [8192,1024] @ [1024,3072] + b  -> g_qkv
    {
        dim3 grid(3 * D_ / 128, (B_ * S_) / 128);
        gemm_tf32_kernel<<<grid, 256, SMEM_BYTES>>>(x, W_qkv, b_qkv, qkv,
                                                    B_ * S_, 3 * D_, D_);
    }

    // 2) Tensor-core causal flash attention -> g_attn
    {
        dim3 grid(S_ / 128, B_ * H_);
        attention_tc_kernel<<<grid, 256, ATT_SMEM_BYTES>>>(qkv, attn);
    }

    // 3) Output projection: [8192,1024] @ [1024,1024] + b -> d_out
    {
        dim3 grid(D_ / 128, (B_ * S_) / 128);
        gemm_tf32_kernel<<<grid, 256, SMEM_BYTES>>>(attn, W_out, b_out, out,
                                                    B_ * S_, D_, D_);
    }
}

// round 4
// speedup vs baseline: 3.6794x; 1.0141x over previous
#include <cuda_runtime.h>
#include <cstdint>

// Problem constants
#define B_  8
#define S_  1024
#define D_  1024
#define H_  16
#define DH_ 64

// Scratch buffers (allocation-free rule: __device__ globals)
__device__ float g_qkv[(size_t)B_ * S_ * 3 * D_];   // [B, S, 3D] tf32-rounded
__device__ float g_attn[(size_t)B_ * S_ * D_];      // [B, S, D]  tf32-rounded
__device__ float g_x[(size_t)B_ * S_ * D_];         // tf32-rounded copy of x
__device__ float g_wqkv[(size_t)D_ * 3 * D_];       // tf32-rounded W_qkv
__device__ float g_wout[(size_t)D_ * D_];           // tf32-rounded W_out

// ---------------------------------------------------------------------------
// TF32 helpers
// ---------------------------------------------------------------------------
__device__ __forceinline__ uint32_t f2tf32(float f) {
    uint32_t r;
    asm("cvt.rna.tf32.f32 %0, %1;" : "=r"(r) : "f"(f));
    return r;
}
__device__ __forceinline__ float tf32r(float f) {
    return __uint_as_float(f2tf32(f));
}

__device__ __forceinline__ void mma_tf32(
    float& d0, float& d1, float& d2, float& d3,
    uint32_t a0, uint32_t a1, uint32_t a2, uint32_t a3,
    uint32_t b0, uint32_t b1)
{
    asm volatile(
        "mma.sync.aligned.m16n8k8.row.col.f32.tf32.tf32.f32 "
        "{%0,%1,%2,%3}, {%4,%5,%6,%7}, {%8,%9}, {%0,%1,%2,%3};"
        : "+f"(d0), "+f"(d1), "+f"(d2), "+f"(d3)
        : "r"(a0), "r"(a1), "r"(a2), "r"(a3), "r"(b0), "r"(b1));
}

__device__ __forceinline__ void cp_async16(uint32_t s, const void* g) {
    asm volatile("cp.async.cg.shared.global [%0], [%1], 16;" :: "r"(s), "l"(g));
}
__device__ __forceinline__ uint32_t smem_u32(const void* p) {
    return (uint32_t)__cvta_generic_to_shared(p);
}

// ---------------------------------------------------------------------------
// Elementwise tf32 pre-round (float4 grid-stride)
// ---------------------------------------------------------------------------
__global__ void round_tf32_kernel(const float* __restrict__ in,
                                  float* __restrict__ out, int n4)
{
    int i = blockIdx.x * blockDim.x + threadIdx.x;
    if (i < n4) {
        float4 v = reinterpret_cast<const float4*>(in)[i];
        v.x = tf32r(v.x); v.y = tf32r(v.y);
        v.z = tf32r(v.z); v.w = tf32r(v.w);
        reinterpret_cast<float4*>(out)[i] = v;
    }
}

// ---------------------------------------------------------------------------
// TF32 tensor-core GEMM + bias. Inputs MUST be tf32-pre-rounded.
// Inner loop feeds raw bits to mma (no cvt). ROUND_OUT rounds the result
// to tf32 for downstream consumption.
// ---------------------------------------------------------------------------
#define AS_STRIDE 36
#define BS_STRIDE 136
#define A_TILE_F (128 * AS_STRIDE)
#define B_TILE_F (32 * BS_STRIDE)
#define BUF_F    (A_TILE_F + B_TILE_F)
#define SMEM_BYTES (2 * BUF_F * 4)

template<bool ROUND_OUT>
__global__ __launch_bounds__(256, 2) void gemm_tf32_kernel(
    const float* __restrict__ A, const float* __restrict__ W,
    const float* __restrict__ bias, float* __restrict__ C,
    int M, int N, int K)
{
    extern __shared__ float sm[];

    const int tid  = threadIdx.x;
    const int lane = tid & 31;
    const int warp = tid >> 5;
    const int wm   = warp & 1;
    const int wn   = warp >> 1;
    const int mBase = blockIdx.y * 128;
    const int nBase = blockIdx.x * 128;
    const int g  = lane >> 2;
    const int t  = lane & 3;

    float acc[4][4][4];
    #pragma unroll
    for (int mt = 0; mt < 4; ++mt)
        #pragma unroll
        for (int nt = 0; nt < 4; ++nt)
            #pragma unroll
            for (int f = 0; f < 4; ++f) acc[mt][nt][f] = 0.0f;

    auto loadTile = [&](int buf, int k0) {
        float* As = sm + buf * BUF_F;
        float* Bs = As + A_TILE_F;
        #pragma unroll
        for (int j = 0; j < 4; ++j) {
            int idx = tid + j * 256;
            int r = idx >> 3, c4 = idx & 7;
            cp_async16(smem_u32(As + r * AS_STRIDE + c4 * 4),
                       &A[(size_t)(mBase + r) * K + k0 + c4 * 4]);
        }
        #pragma unroll
        for (int j = 0; j < 4; ++j) {
            int idx = tid + j * 256;
            int r = idx >> 5, c4 = idx & 31;
            cp_async16(smem_u32(Bs + r * BS_STRIDE + c4 * 4),
                       &W[(size_t)(k0 + r) * N + nBase + c4 * 4]);
        }
        asm volatile("cp.async.commit_group;");
    };

    const int nIter = K / 32;
    loadTile(0, 0);

    for (int it = 0; it < nIter; ++it) {
        if (it + 1 < nIter) {
            loadTile((it + 1) & 1, (it + 1) * 32);
            asm volatile("cp.async.wait_group 1;");
        } else {
            asm volatile("cp.async.wait_group 0;");
        }
        __syncthreads();

        const uint32_t* As = reinterpret_cast<const uint32_t*>(sm + (it & 1) * BUF_F);
        const uint32_t* Bs = As + A_TILE_F;

        #pragma unroll
        for (int kk = 0; kk < 4; ++kk) {
            const int kc = kk * 8;

            uint32_t af[4][4];
            #pragma unroll
            for (int mt = 0; mt < 4; ++mt) {
                int r = wm * 64 + mt * 16 + g;
                af[mt][0] = As[(r    ) * AS_STRIDE + kc + t    ];
                af[mt][1] = As[(r + 8) * AS_STRIDE + kc + t    ];
                af[mt][2] = As[(r    ) * AS_STRIDE + kc + t + 4];
                af[mt][3] = As[(r + 8) * AS_STRIDE + kc + t + 4];
            }
            uint32_t bf[4][2];
            #pragma unroll
            for (int nt = 0; nt < 4; ++nt) {
                int n = wn * 32 + nt * 8 + g;
                bf[nt][0] = Bs[(kc + t    ) * BS_STRIDE + n];
                bf[nt][1] = Bs[(kc + t + 4) * BS_STRIDE + n];
            }
            #pragma unroll
            for (int mt = 0; mt < 4; ++mt)
                #pragma unroll
                for (int nt = 0; nt < 4; ++nt)
                    mma_tf32(acc[mt][nt][0], acc[mt][nt][1],
                             acc[mt][nt][2], acc[mt][nt][3],
                             af[mt][0], af[mt][1], af[mt][2], af[mt][3],
                             bf[nt][0], bf[nt][1]);
        }
        __syncthreads();
    }

    #pragma unroll
    for (int mt = 0; mt < 4; ++mt) {
        int r0 = mBase + wm * 64 + mt * 16 + g;
        int r1 = r0 + 8;
        #pragma unroll
        for (int nt = 0; nt < 4; ++nt) {
            int col = nBase + wn * 32 + nt * 8 + t * 2;
            float2 bv = *reinterpret_cast<const float2*>(&bias[col]);
            float2 v0, v1;
            v0.x = acc[mt][nt][0] + bv.x;
            v0.y = acc[mt][nt][1] + bv.y;
            v1.x = acc[mt][nt][2] + bv.x;
            v1.y = acc[mt][nt][3] + bv.y;
            if (ROUND_OUT) {
                v0.x = tf32r(v0.x); v0.y = tf32r(v0.y);
                v1.x = tf32r(v1.x); v1.y = tf32r(v1.y);
            }
            *reinterpret_cast<float2*>(&C[(size_t)r0 * N + col]) = v0;
            *reinterpret_cast<float2*>(&C[(size_t)r1 * N + col]) = v1;
        }
    }
}

// ---------------------------------------------------------------------------
// Tensor-core FlashAttention (tf32, causal). qkv is tf32-pre-rounded, so
// Q/K/V fragments are raw bit loads; only computed P values need cvt.
// Block = 128 query rows of one (b,h); 256 threads = 8 warps, 16 rows/warp.
// grid = (8, B*H). Output written tf32-rounded.
// ---------------------------------------------------------------------------
#define QP_STRIDE 68
#define K_STRIDE  68
#define V_STRIDE  72
#define QP_F (128 * QP_STRIDE)
#define K_F  (64 * K_STRIDE)
#define V_F  (64 * V_STRIDE)
#define ATT_SMEM_BYTES ((QP_F + K_F + V_F) * 4)

__global__ __launch_bounds__(256, 2) void attention_tc_kernel(
    const float* __restrict__ qkv, float* __restrict__ attn)
{
    extern __shared__ float sm[];
    float* QP = sm;
    float* Ks = sm + QP_F;
    float* Vs = Ks + K_F;
    uint32_t* QPu = reinterpret_cast<uint32_t*>(QP);
    const uint32_t* Ksu = reinterpret_cast<const uint32_t*>(Ks);
    const uint32_t* Vsu = reinterpret_cast<const uint32_t*>(Vs);

    const int tid  = threadIdx.x;
    const int lane = tid & 31;
    const int warp = tid >> 5;
    const int g = lane >> 2;
    const int t = lane & 3;
    const int q0 = (7 - blockIdx.x) * 128;   // heavy tiles first
    const int bh = blockIdx.y;
    const int b  = bh >> 4;
    const int h  = bh & 15;

    const float* qbase = qkv + (size_t)b * S_ * 3072 + h * DH_;
    const float* kbase = qbase + D_;
    const float* vbase = qbase + 2 * D_;

    // ---- Load Q tile (scaled by 1/8 = exact exponent shift) ----
    #pragma unroll
    for (int i = 0; i < 8; ++i) {
        int idx = tid + i * 256;
        int r = idx >> 4, c4 = idx & 15;
        float4 v = *reinterpret_cast<const float4*>(
            qbase + (size_t)(q0 + r) * 3072 + c4 * 4);
        v.x *= 0.125f; v.y *= 0.125f; v.z *= 0.125f; v.w *= 0.125f;
        *reinterpret_cast<float4*>(QP + r * QP_STRIDE + c4 * 4) = v;
    }
    __syncthreads();

    // ---- Build Q fragments (raw bits, data already tf32) ----
    const int rowA = warp * 16 + g;
    uint32_t qf[8][4];
    #pragma unroll
    for (int kk = 0; kk < 8; ++kk) {
        int c = kk * 8;
        qf[kk][0] = QPu[(rowA    ) * QP_STRIDE + c + t    ];
        qf[kk][1] = QPu[(rowA + 8) * QP_STRIDE + c + t    ];
        qf[kk][2] = QPu[(rowA    ) * QP_STRIDE + c + t + 4];
        qf[kk][3] = QPu[(rowA + 8) * QP_STRIDE + c + t + 4];
    }

    float of[8][4];
    #pragma unroll
    for (int nt = 0; nt < 8; ++nt)
        #pragma unroll
        for (int f = 0; f < 4; ++f) of[nt][f] = 0.0f;
    float m0 = -1e30f, m1 = -1e30f, l0 = 0.0f, l1 = 0.0f;

    const int nTiles = q0 / 64 + 2;
    for (int kt = 0; kt < nTiles; ++kt) {
        const int ks = kt * 64;
        __syncthreads();

        // ---- Load K,V tiles ----
        #pragma unroll
        for (int i = 0; i < 4; ++i) {
            int idx = tid + i * 256;
            int r = idx >> 4, c4 = idx & 15;
            *reinterpret_cast<float4*>(Ks + r * K_STRIDE + c4 * 4) =
                *reinterpret_cast<const float4*>(
                    kbase + (size_t)(ks + r) * 3072 + c4 * 4);
            *reinterpret_cast<float4*>(Vs + r * V_STRIDE + c4 * 4) =
                *reinterpret_cast<const float4*>(
                    vbase + (size_t)(ks + r) * 3072 + c4 * 4);
        }
        __syncthreads();

        // ---- S = (Q/8) @ K^T ----
        float sv[8][4];
        #pragma unroll
        for (int nt = 0; nt < 8; ++nt) {
            sv[nt][0] = sv[nt][1] = sv[nt][2] = sv[nt][3] = 0.0f;
            #pragma unroll
            for (int kk = 0; kk < 8; ++kk) {
                uint32_t b0 = Ksu[(nt * 8 + g) * K_STRIDE + kk * 8 + t    ];
                uint32_t b1 = Ksu[(nt * 8 + g) * K_STRIDE + kk * 8 + t + 4];
                mma_tf32(sv[nt][0], sv[nt][1], sv[nt][2], sv[nt][3],
                         qf[kk][0], qf[kk][1], qf[kk][2], qf[kk][3], b0, b1);
            }
        }

        // ---- Causal mask (only diagonal tiles) ----
        if (ks >= q0) {
            int r0 = q0 + rowA, r1 = r0 + 8;
            #pragma unroll
            for (int nt = 0; nt < 8; ++nt) {
                int c0 = ks + nt * 8 + 2 * t, c1 = c0 + 1;
                if (c0 > r0) sv[nt][0] = -1e30f;
                if (c1 > r0) sv[nt][1] = -1e30f;
                if (c0 > r1) sv[nt][2] = -1e30f;
                if (c1 > r1) sv[nt][3] = -1e30f;
            }
        }

        // ---- Online softmax ----
        float rx0 = -1e30f, rx1 = -1e30f;
        #pragma unroll
        for (int nt = 0; nt < 8; ++nt) {
            rx0 = fmaxf(rx0, fmaxf(sv[nt][0], sv[nt][1]));
            rx1 = fmaxf(rx1, fmaxf(sv[nt][2], sv[nt][3]));
        }
        rx0 = fmaxf(rx0, __shfl_xor_sync(0xffffffffu, rx0, 1));
        rx0 = fmaxf(rx0, __shfl_xor_sync(0xffffffffu, rx0, 2));
        rx1 = fmaxf(rx1, __shfl_xor_sync(0xffffffffu, rx1, 1));
        rx1 = fmaxf(rx1, __shfl_xor_sync(0xffffffffu, rx1, 2));

        float mn0 = fmaxf(m0, rx0), mn1 = fmaxf(m1, rx1);
        float corr0 = __expf(m0 - mn0), corr1 = __expf(m1 - mn1);
        m0 = mn0; m1 = mn1;

        float ps0 = 0.0f, ps1 = 0.0f;
        #pragma unroll
        for (int nt = 0; nt < 8; ++nt) {
            float p0 = __expf(sv[nt][0] - m0);
            float p1 = __expf(sv[nt][1] - m0);
            float p2 = __expf(sv[nt][2] - m1);
            float p3 = __expf(sv[nt][3] - m1);
            ps0 += p0 + p1;
            ps1 += p2 + p3;
            uint2 w0; w0.x = f2tf32(p0); w0.y = f2tf32(p1);
            uint2 w1; w1.x = f2tf32(p2); w1.y = f2tf32(p3);
            *reinterpret_cast<uint2*>(QPu + (rowA    ) * QP_STRIDE + nt * 8 + 2 * t) = w0;
            *reinterpret_cast<uint2*>(QPu + (rowA + 8) * QP_STRIDE + nt * 8 + 2 * t) = w1;
        }
        ps0 += __shfl_xor_sync(0xffffffffu, ps0, 1);
        ps0 += __shfl_xor_sync(0xffffffffu, ps0, 2);
        ps1 += __shfl_xor_sync(0xffffffffu, ps1, 1);
        ps1 += __shfl_xor_sync(0xffffffffu, ps1, 2);
        l0 = l0 * corr0 + ps0;
        l1 = l1 * corr1 + ps1;

        #pragma unroll
        for (int nt = 0; nt < 8; ++nt) {
            of[nt][0] *= corr0; of[nt][1] *= corr0;
            of[nt][2] *= corr1; of[nt][3] *= corr1;
        }
        __syncwarp();   // P rows are warp-private: order STS before LDS

        // ---- O += P @ V ----
        #pragma unroll
        for (int kk = 0; kk < 8; ++kk) {
            uint32_t a0 = QPu[(rowA    ) * QP_STRIDE + kk * 8 + t    ];
            uint32_t a1 = QPu[(rowA + 8) * QP_STRIDE + kk * 8 + t    ];
            uint32_t a2 = QPu[(rowA    ) * QP_STRIDE + kk * 8 + t + 4];
            uint32_t a3 = QPu[(rowA + 8) * QP_STRIDE + kk * 8 + t + 4];
            #pragma unroll
            for (int nt = 0; nt < 8; ++nt) {
                uint32_t b0 = Vsu[(kk * 8 + t    ) * V_STRIDE + nt * 8 + g];
                uint32_t b1 = Vsu[(kk * 8 + t + 4) * V_STRIDE + nt * 8 + g];
                mma_tf32(of[nt][0], of[nt][1], of[nt][2], of[nt][3],
                         a0, a1, a2, a3, b0, b1);
            }
        }
    }

    // ---- Normalize, round to tf32, store head-regrouped ----
    const float inv0 = 1.0f / l0;
    const float inv1 = 1.0f / l1;
    const int r0 = q0 + rowA;
    float* obase = attn + ((size_t)b * S_ + r0) * D_ + h * DH_;
    #pragma unroll
    for (int nt = 0; nt < 8; ++nt) {
        int col = nt * 8 + 2 * t;
        float2 v0, v1;
        v0.x = tf32r(of[nt][0] * inv0); v0.y = tf32r(of[nt][1] * inv0);
        v1.x = tf32r(of[nt][2] * inv1); v1.y = tf32r(of[nt][3] * inv1);
        *reinterpret_cast<float2*>(obase + col) = v0;
        *reinterpret_cast<float2*>(obase + 8 * (size_t)D_ + col) = v1;
    }
}

// ---------------------------------------------------------------------------
// Launch
// ---------------------------------------------------------------------------
extern "C" void kernel_launch(void* const* d_in, const int* in_sizes, int n_in,
                              void* d_out, int out_size)
{
    (void)in_sizes; (void)n_in; (void)out_size;
    const float* x     = (const float*)d_in[0];
    const float* W_qkv = (const float*)d_in[1];
    const float* b_qkv = (const float*)d_in[2];
    const float* W_out = (const float*)d_in[3];
    const float* b_out = (const float*)d_in[4];
    float* out = (float*)d_out;

    float *qkv, *attn, *xr, *wqkvr, *woutr;
    cudaGetSymbolAddress((void**)&qkv,   g_qkv);
    cudaGetSymbolAddress((void**)&attn,  g_attn);
    cudaGetSymbolAddress((void**)&xr,    g_x);
    cudaGetSymbolAddress((void**)&wqkvr, g_wqkv);
    cudaGetSymbolAddress((void**)&woutr, g_wout);

    cudaFuncSetAttribute(gemm_tf32_kernel<true>,
                         cudaFuncAttributeMaxDynamicSharedMemorySize, SMEM_BYTES);
    cudaFuncSetAttribute(gemm_tf32_kernel<false>,
                         cudaFuncAttributeMaxDynamicSharedMemorySize, SMEM_BYTES);
    cudaFuncSetAttribute(attention_tc_kernel,
                         cudaFuncAttributeMaxDynamicSharedMemorySize, ATT_SMEM_BYTES);

    // 0) Pre-round inputs to tf32-representable fp32
    {
        int nx = B_ * S_ * D_ / 4;
        round_tf32_kernel<<<(nx + 255) / 256, 256>>>(x, xr, nx);
        int nw = D_ * 3 * D_ / 4;
        round_tf32_kernel<<<(nw + 255) / 256, 256>>>(W_qkv, wqkvr, nw);
        int no = D_ * D_ / 4;
        round_tf32_kernel<<<(no + 255) / 256, 256>>>(W_out, woutr, no);
    }

    // 1) QKV projection -> g_qkv (tf32-rounded output)
    {
        dim3 grid(3 * D_ / 128, (B_ * S_) / 128);
        gemm_tf32_kernel<true><<<grid, 256, SMEM_BYTES>>>(xr, wqkvr, b_qkv, qkv,
                                                          B_ * S_, 3 * D_, D_);
    }

    // 2) Tensor-core causal flash attention -> g_attn (tf32-rounded)
    {
        dim3 grid(S_ / 128, B_ * H_);
        attention_tc_kernel<<<grid, 256, ATT_SMEM_BYTES>>>(qkv, attn);
    }

    // 3) Output projection -> d_out (full fp32 output)
    {
        dim3 grid(D_ / 128, (B_ * S_) / 128);
        gemm_tf32_kernel<false><<<grid, 256, SMEM_BYTES>>>(attn, woutr, b_out, out,
                                                           B_ * S_, D_, D_);
    }
}

// round 5
// speedup vs baseline: 3.8063x; 1.0345x over previous
#include <cuda_runtime.h>
#include <cstdint>

// Problem constants
#define B_  8
#define S_  1024
#define D_  1024
#define H_  16
#define DH_ 64

// Scratch buffers (allocation-free rule: __device__ globals)
__device__ float g_qkv[(size_t)B_ * S_ * 3 * D_];   // [B, S, 3D] tf32-rounded
__device__ float g_attn[(size_t)B_ * S_ * D_];      // [B, S, D]  tf32-rounded
__device__ float g_x[(size_t)B_ * S_ * D_];         // tf32-rounded copy of x
__device__ float g_wqkv[(size_t)D_ * 3 * D_];       // tf32-rounded W_qkv
__device__ float g_wout[(size_t)D_ * D_];           // tf32-rounded W_out

// ---------------------------------------------------------------------------
// TF32 helpers
// ---------------------------------------------------------------------------
__device__ __forceinline__ uint32_t f2tf32(float f) {
    uint32_t r;
    asm("cvt.rna.tf32.f32 %0, %1;" : "=r"(r) : "f"(f));
    return r;
}
__device__ __forceinline__ float tf32r(float f) {
    return __uint_as_float(f2tf32(f));
}

__device__ __forceinline__ void mma_tf32(
    float& d0, float& d1, float& d2, float& d3,
    uint32_t a0, uint32_t a1, uint32_t a2, uint32_t a3,
    uint32_t b0, uint32_t b1)
{
    asm volatile(
        "mma.sync.aligned.m16n8k8.row.col.f32.tf32.tf32.f32 "
        "{%0,%1,%2,%3}, {%4,%5,%6,%7}, {%8,%9}, {%0,%1,%2,%3};"
        : "+f"(d0), "+f"(d1), "+f"(d2), "+f"(d3)
        : "r"(a0), "r"(a1), "r"(a2), "r"(a3), "r"(b0), "r"(b1));
}

__device__ __forceinline__ void cp_async16(uint32_t s, const void* g) {
    asm volatile("cp.async.cg.shared.global [%0], [%1], 16;" :: "r"(s), "l"(g));
}
__device__ __forceinline__ uint32_t smem_u32(const void* p) {
    return (uint32_t)__cvta_generic_to_shared(p);
}

// ---------------------------------------------------------------------------
// Elementwise tf32 pre-round (float4 grid-stride)
// ---------------------------------------------------------------------------
__global__ void round_tf32_kernel(const float* __restrict__ in,
                                  float* __restrict__ out, int n4)
{
    int i = blockIdx.x * blockDim.x + threadIdx.x;
    if (i < n4) {
        float4 v = reinterpret_cast<const float4*>(in)[i];
        v.x = tf32r(v.x); v.y = tf32r(v.y);
        v.z = tf32r(v.z); v.w = tf32r(v.w);
        reinterpret_cast<float4*>(out)[i] = v;
    }
}

// ---------------------------------------------------------------------------
// TF32 GEMM v3: block 128x128, 4 warps (2x2), warp tile 64x64, BK=32,
// 3-stage cp.async pipeline, one barrier per k-iter. Inputs tf32-pre-rounded;
// fragments are raw bit loads. 1.0 LDS per MMA.
// ---------------------------------------------------------------------------
#define AS_STRIDE 36
#define BS_STRIDE 136
#define A_TILE_F (128 * AS_STRIDE)          // 4608 floats
#define B_TILE_F (32 * BS_STRIDE)           // 4352 floats
#define BUF_F    (A_TILE_F + B_TILE_F)      // 8960 floats
#define SMEM_BYTES (3 * BUF_F * 4)          // 107520 bytes (3 stages)

template<bool ROUND_OUT>
__global__ __launch_bounds__(128, 2) void gemm_tf32_kernel(
    const float* __restrict__ A, const float* __restrict__ W,
    const float* __restrict__ bias, float* __restrict__ C,
    int M, int N, int K)
{
    extern __shared__ float sm[];

    const int tid  = threadIdx.x;
    const int lane = tid & 31;
    const int warp = tid >> 5;       // 0..3
    const int wm   = warp & 1;       // 0..1
    const int wn   = warp >> 1;      // 0..1
    const int mBase = blockIdx.y * 128;
    const int nBase = blockIdx.x * 128;
    const int g  = lane >> 2;        // 0..7
    const int t  = lane & 3;         // 0..3

    float acc[4][8][4];              // [mt][nt][frag]
    #pragma unroll
    for (int mt = 0; mt < 4; ++mt)
        #pragma unroll
        for (int nt = 0; nt < 8; ++nt)
            #pragma unroll
            for (int f = 0; f < 4; ++f) acc[mt][nt][f] = 0.0f;

    auto loadTile = [&](int buf, int k0) {
        float* As = sm + buf * BUF_F;
        float* Bs = As + A_TILE_F;
        #pragma unroll
        for (int j = 0; j < 8; ++j) {          // A: 128x32 = 1024 float4
            int idx = tid + j * 128;
            int r = idx >> 3, c4 = idx & 7;
            cp_async16(smem_u32(As + r * AS_STRIDE + c4 * 4),
                       &A[(size_t)(mBase + r) * K + k0 + c4 * 4]);
        }
        #pragma unroll
        for (int j = 0; j < 8; ++j) {          // B: 32x128 = 1024 float4
            int idx = tid + j * 128;
            int r = idx >> 5, c4 = idx & 31;
            cp_async16(smem_u32(Bs + r * BS_STRIDE + c4 * 4),
                       &W[(size_t)(k0 + r) * N + nBase + c4 * 4]);
        }
        asm volatile("cp.async.commit_group;");
    };

    const int nIter = K / 32;        // 32
    loadTile(0, 0);
    loadTile(1, 32);

    for (int it = 0; it < nIter; ++it) {
        if (it + 1 < nIter) {
            asm volatile("cp.async.wait_group 1;");   // tile `it` resident
        } else {
            asm volatile("cp.async.wait_group 0;");
        }
        __syncthreads();   // tile `it` visible; everyone done with buf (it-1)%3

        if (it + 2 < nIter)
            loadTile((it + 2) % 3, (it + 2) * 32);    // overwrites buf (it-1)%3

        const uint32_t* As = reinterpret_cast<const uint32_t*>(sm + (it % 3) * BUF_F);
        const uint32_t* Bs = As + A_TILE_F;

        #pragma unroll
        for (int kk = 0; kk < 4; ++kk) {
            const int kc = kk * 8;

            uint32_t af[4][4];
            #pragma unroll
            for (int mt = 0; mt < 4; ++mt) {
                int r = wm * 64 + mt * 16 + g;
                af[mt][0] = As[(r    ) * AS_STRIDE + kc + t    ];
                af[mt][1] = As[(r + 8) * AS_STRIDE + kc + t    ];
                af[mt][2] = As[(r    ) * AS_STRIDE + kc + t + 4];
                af[mt][3] = As[(r + 8) * AS_STRIDE + kc + t + 4];
            }
            uint32_t bf[8][2];
            #pragma unroll
            for (int nt = 0; nt < 8; ++nt) {
                int n = wn * 64 + nt * 8 + g;
                bf[nt][0] = Bs[(kc + t    ) * BS_STRIDE + n];
                bf[nt][1] = Bs[(kc + t + 4) * BS_STRIDE + n];
            }
            #pragma unroll
            for (int mt = 0; mt < 4; ++mt)
                #pragma unroll
                for (int nt = 0; nt < 8; ++nt)
                    mma_tf32(acc[mt][nt][0], acc[mt][nt][1],
                             acc[mt][nt][2], acc[mt][nt][3],
                             af[mt][0], af[mt][1], af[mt][2], af[mt][3],
                             bf[nt][0], bf[nt][1]);
        }
    }

    // ---- epilogue: bias add, float2 stores ----
    #pragma unroll
    for (int mt = 0; mt < 4; ++mt) {
        int r0 = mBase + wm * 64 + mt * 16 + g;
        int r1 = r0 + 8;
        #pragma unroll
        for (int nt = 0; nt < 8; ++nt) {
            int col = nBase + wn * 64 + nt * 8 + t * 2;
            float2 bv = *reinterpret_cast<const float2*>(&bias[col]);
            float2 v0, v1;
            v0.x = acc[mt][nt][0] + bv.x;
            v0.y = acc[mt][nt][1] + bv.y;
            v1.x = acc[mt][nt][2] + bv.x;
            v1.y = acc[mt][nt][3] + bv.y;
            if (ROUND_OUT) {
                v0.x = tf32r(v0.x); v0.y = tf32r(v0.y);
                v1.x = tf32r(v1.x); v1.y = tf32r(v1.y);
            }
            *reinterpret_cast<float2*>(&C[(size_t)r0 * N + col]) = v0;
            *reinterpret_cast<float2*>(&C[(size_t)r1 * N + col]) = v1;
        }
    }
}

// ---------------------------------------------------------------------------
// Tensor-core FlashAttention (tf32, causal) — unchanged from R4.
// ---------------------------------------------------------------------------
#define QP_STRIDE 68
#define K_STRIDE  68
#define V_STRIDE  72
#define QP_F (128 * QP_STRIDE)
#define K_F  (64 * K_STRIDE)
#define V_F  (64 * V_STRIDE)
#define ATT_SMEM_BYTES ((QP_F + K_F + V_F) * 4)

__global__ __launch_bounds__(256, 2) void attention_tc_kernel(
    const float* __restrict__ qkv, float* __restrict__ attn)
{
    extern __shared__ float sm[];
    float* QP = sm;
    float* Ks = sm + QP_F;
    float* Vs = Ks + K_F;
    uint32_t* QPu = reinterpret_cast<uint32_t*>(QP);
    const uint32_t* Ksu = reinterpret_cast<const uint32_t*>(Ks);
    const uint32_t* Vsu = reinterpret_cast<const uint32_t*>(Vs);

    const int tid  = threadIdx.x;
    const int lane = tid & 31;
    const int warp = tid >> 5;
    const int g = lane >> 2;
    const int t = lane & 3;
    const int q0 = (7 - blockIdx.x) * 128;
    const int bh = blockIdx.y;
    const int b  = bh >> 4;
    const int h  = bh & 15;

    const float* qbase = qkv + (size_t)b * S_ * 3072 + h * DH_;
    const float* kbase = qbase + D_;
    const float* vbase = qbase + 2 * D_;

    #pragma unroll
    for (int i = 0; i < 8; ++i) {
        int idx = tid + i * 256;
        int r = idx >> 4, c4 = idx & 15;
        float4 v = *reinterpret_cast<const float4*>(
            qbase + (size_t)(q0 + r) * 3072 + c4 * 4);
        v.x *= 0.125f; v.y *= 0.125f; v.z *= 0.125f; v.w *= 0.125f;
        *reinterpret_cast<float4*>(QP + r * QP_STRIDE + c4 * 4) = v;
    }
    __syncthreads();

    const int rowA = warp * 16 + g;
    uint32_t qf[8][4];
    #pragma unroll
    for (int kk = 0; kk < 8; ++kk) {
        int c = kk * 8;
        qf[kk][0] = QPu[(rowA    ) * QP_STRIDE + c + t    ];
        qf[kk][1] = QPu[(rowA + 8) * QP_STRIDE + c + t    ];
        qf[kk][2] = QPu[(rowA    ) * QP_STRIDE + c + t + 4];
        qf[kk][3] = QPu[(rowA + 8) * QP_STRIDE + c + t + 4];
    }

    float of[8][4];
    #pragma unroll
    for (int nt = 0; nt < 8; ++nt)
        #pragma unroll
        for (int f = 0; f < 4; ++f) of[nt][f] = 0.0f;
    float m0 = -1e30f, m1 = -1e30f, l0 = 0.0f, l1 = 0.0f;

    const int nTiles = q0 / 64 + 2;
    for (int kt = 0; kt < nTiles; ++kt) {
        const int ks = kt * 64;
        __syncthreads();

        #pragma unroll
        for (int i = 0; i < 4; ++i) {
            int idx = tid + i * 256;
            int r = idx >> 4, c4 = idx & 15;
            *reinterpret_cast<float4*>(Ks + r * K_STRIDE + c4 * 4) =
                *reinterpret_cast<const float4*>(
                    kbase + (size_t)(ks + r) * 3072 + c4 * 4);
            *reinterpret_cast<float4*>(Vs + r * V_STRIDE + c4 * 4) =
                *reinterpret_cast<const float4*>(
                    vbase + (size_t)(ks + r) * 3072 + c4 * 4);
        }
        __syncthreads();

        float sv[8][4];
        #pragma unroll
        for (int nt = 0; nt < 8; ++nt) {
            sv[nt][0] = sv[nt][1] = sv[nt][2] = sv[nt][3] = 0.0f;
            #pragma unroll
            for (int kk = 0; kk < 8; ++kk) {
                uint32_t b0 = Ksu[(nt * 8 + g) * K_STRIDE + kk * 8 + t    ];
                uint32_t b1 = Ksu[(nt * 8 + g) * K_STRIDE + kk * 8 + t + 4];
                mma_tf32(sv[nt][0], sv[nt][1], sv[nt][2], sv[nt][3],
                         qf[kk][0], qf[kk][1], qf[kk][2], qf[kk][3], b0, b1);
            }
        }

        if (ks >= q0) {
            int r0 = q0 + rowA, r1 = r0 + 8;
            #pragma unroll
            for (int nt = 0; nt < 8; ++nt) {
                int c0 = ks + nt * 8 + 2 * t, c1 = c0 + 1;
                if (c0 > r0) sv[nt][0] = -1e30f;
                if (c1 > r0) sv[nt][1] = -1e30f;
                if (c0 > r1) sv[nt][2] = -1e30f;
                if (c1 > r1) sv[nt][3] = -1e30f;
            }
        }

        float rx0 = -1e30f, rx1 = -1e30f;
        #pragma unroll
        for (int nt = 0; nt < 8; ++nt) {
            rx0 = fmaxf(rx0, fmaxf(sv[nt][0], sv[nt][1]));
            rx1 = fmaxf(rx1, fmaxf(sv[nt][2], sv[nt][3]));
        }
        rx0 = fmaxf(rx0, __shfl_xor_sync(0xffffffffu, rx0, 1));
        rx0 = fmaxf(rx0, __shfl_xor_sync(0xffffffffu, rx0, 2));
        rx1 = fmaxf(rx1, __shfl_xor_sync(0xffffffffu, rx1, 1));
        rx1 = fmaxf(rx1, __shfl_xor_sync(0xffffffffu, rx1, 2));

        float mn0 = fmaxf(m0, rx0), mn1 = fmaxf(m1, rx1);
        float corr0 = __expf(m0 - mn0), corr1 = __expf(m1 - mn1);
        m0 = mn0; m1 = mn1;

        float ps0 = 0.0f, ps1 = 0.0f;
        #pragma unroll
        for (int nt = 0; nt < 8; ++nt) {
            float p0 = __expf(sv[nt][0] - m0);
            float p1 = __expf(sv[nt][1] - m0);
            float p2 = __expf(sv[nt][2] - m1);
            float p3 = __expf(sv[nt][3] - m1);
            ps0 += p0 + p1;
            ps1 += p2 + p3;
            uint2 w0; w0.x = f2tf32(p0); w0.y = f2tf32(p1);
            uint2 w1; w1.x = f2tf32(p2); w1.y = f2tf32(p3);
            *reinterpret_cast<uint2*>(QPu + (rowA    ) * QP_STRIDE + nt * 8 + 2 * t) = w0;
            *reinterpret_cast<uint2*>(QPu + (rowA + 8) * QP_STRIDE + nt * 8 + 2 * t) = w1;
        }
        ps0 += __shfl_xor_sync(0xffffffffu, ps0, 1);
        ps0 += __shfl_xor_sync(0xffffffffu, ps0, 2);
        ps1 += __shfl_xor_sync(0xffffffffu, ps1, 1);
        ps1 += __shfl_xor_sync(0xffffffffu, ps1, 2);
        l0 = l0 * corr0 + ps0;
        l1 = l1 * corr1 + ps1;

        #pragma unroll
        for (int nt = 0; nt < 8; ++nt) {
            of[nt][0] *= corr0; of[nt][1] *= corr0;
            of[nt][2] *= corr1; of[nt][3] *= corr1;
        }
        __syncwarp();

        #pragma unroll
        for (int kk = 0; kk < 8; ++kk) {
            uint32_t a0 = QPu[(rowA    ) * QP_STRIDE + kk * 8 + t    ];
            uint32_t a1 = QPu[(rowA + 8) * QP_STRIDE + kk * 8 + t    ];
            uint32_t a2 = QPu[(rowA    ) * QP_STRIDE + kk * 8 + t + 4];
            uint32_t a3 = QPu[(rowA + 8) * QP_STRIDE + kk * 8 + t + 4];
            #pragma unroll
            for (int nt = 0; nt < 8; ++nt) {
                uint32_t b0 = Vsu[(kk * 8 + t    ) * V_STRIDE + nt * 8 + g];
                uint32_t b1 = Vsu[(kk * 8 + t + 4) * V_STRIDE + nt * 8 + g];
                mma_tf32(of[nt][0], of[nt][1], of[nt][2], of[nt][3],
                         a0, a1, a2, a3, b0, b1);
            }
        }
    }

    const float inv0 = 1.0f / l0;
    const float inv1 = 1.0f / l1;
    const int r0 = q0 + rowA;
    float* obase = attn + ((size_t)b * S_ + r0) * D_ + h * DH_;
    #pragma unroll
    for (int nt = 0; nt < 8; ++nt) {
        int col = nt * 8 + 2 * t;
        float2 v0, v1;
        v0.x = tf32r(of[nt][0] * inv0); v0.y = tf32r(of[nt][1] * inv0);
        v1.x = tf32r(of[nt][2] * inv1); v1.y = tf32r(of[nt][3] * inv1);
        *reinterpret_cast<float2*>(obase + col) = v0;
        *reinterpret_cast<float2*>(obase + 8 * (size_t)D_ + col) = v1;
    }
}

// ---------------------------------------------------------------------------
// Launch
// ---------------------------------------------------------------------------
extern "C" void kernel_launch(void* const* d_in, const int* in_sizes, int n_in,
                              void* d_out, int out_size)
{
    (void)in_sizes; (void)n_in; (void)out_size;
    const float* x     = (const float*)d_in[0];
    const float* W_qkv = (const float*)d_in[1];
    const float* b_qkv = (const float*)d_in[2];
    const float* W_out = (const float*)d_in[3];
    const float* b_out = (const float*)d_in[4];
    float* out = (float*)d_out;

    float *qkv, *attn, *xr, *wqkvr, *woutr;
    cudaGetSymbolAddress((void**)&qkv,   g_qkv);
    cudaGetSymbolAddress((void**)&attn,  g_attn);
    cudaGetSymbolAddress((void**)&xr,    g_x);
    cudaGetSymbolAddress((void**)&wqkvr, g_wqkv);
    cudaGetSymbolAddress((void**)&woutr, g_wout);

    cudaFuncSetAttribute(gemm_tf32_kernel<true>,
                         cudaFuncAttributeMaxDynamicSharedMemorySize, SMEM_BYTES);
    cudaFuncSetAttribute(gemm_tf32_kernel<false>,
                         cudaFuncAttributeMaxDynamicSharedMemorySize, SMEM_BYTES);
    cudaFuncSetAttribute(attention_tc_kernel,
                         cudaFuncAttributeMaxDynamicSharedMemorySize, ATT_SMEM_BYTES);

    // 0) Pre-round inputs to tf32-representable fp32
    {
        int nx = B_ * S_ * D_ / 4;
        round_tf32_kernel<<<(nx + 255) / 256, 256>>>(x, xr, nx);
        int nw = D_ * 3 * D_ / 4;
        round_tf32_kernel<<<(nw + 255) / 256, 256>>>(W_qkv, wqkvr, nw);
        int no = D_ * D_ / 4;
        round_tf32_kernel<<<(no + 255) / 256, 256>>>(W_out, woutr, no);
    }

    // 1) QKV projection -> g_qkv (tf32-rounded output)
    {
        dim3 grid(3 * D_ / 128, (B_ * S_) / 128);
        gemm_tf32_kernel<true><<<grid, 128, SMEM_BYTES>>>(xr, wqkvr, b_qkv, qkv,
                                                          B_ * S_, 3 * D_, D_);
    }

    // 2) Tensor-core causal flash attention -> g_attn (tf32-rounded)
    {
        dim3 grid(S_ / 128, B_ * H_);
        attention_tc_kernel<<<grid, 256, ATT_SMEM_BYTES>>>(qkv, attn);
    }

    // 3) Output projection -> d_out (full fp32 output)
    {
        dim3 grid(D_ / 128, (B_ * S_) / 128);
        gemm_tf32_kernel<false><<<grid, 128, SMEM_BYTES>>>(attn, woutr, b_out, out,
                                                           B_ * S_, D_, D_);
    }
}

// round 8
// speedup vs baseline: 3.8269x; 1.0054x over previous
#include <cuda_runtime.h>
#include <cstdint>

// Problem constants
#define B_  8
#define S_  1024
#define D_  1024
#define H_  16
#define DH_ 64

// Scratch buffers (allocation-free rule: __device__ globals)
__device__ float g_qkv[(size_t)B_ * S_ * 3 * D_];   // [B, S, 3D] tf32-rounded
__device__ float g_attn[(size_t)B_ * S_ * D_];      // [B, S, D]  tf32-rounded
__device__ float g_x[(size_t)B_ * S_ * D_];         // tf32-rounded copy of x
__device__ float g_wqkv[(size_t)D_ * 3 * D_];       // tf32-rounded W_qkv
__device__ float g_wout[(size_t)D_ * D_];           // tf32-rounded W_out

// ---------------------------------------------------------------------------
// TF32 helpers
// ---------------------------------------------------------------------------
__device__ __forceinline__ uint32_t f2tf32(float f) {
    uint32_t r;
    asm("cvt.rna.tf32.f32 %0, %1;" : "=r"(r) : "f"(f));
    return r;
}
__device__ __forceinline__ float tf32r(float f) {
    return __uint_as_float(f2tf32(f));
}

__device__ __forceinline__ void mma_tf32(
    float& d0, float& d1, float& d2, float& d3,
    uint32_t a0, uint32_t a1, uint32_t a2, uint32_t a3,
    uint32_t b0, uint32_t b1)
{
    asm volatile(
        "mma.sync.aligned.m16n8k8.row.col.f32.tf32.tf32.f32 "
        "{%0,%1,%2,%3}, {%4,%5,%6,%7}, {%8,%9}, {%0,%1,%2,%3};"
        : "+f"(d0), "+f"(d1), "+f"(d2), "+f"(d3)
        : "r"(a0), "r"(a1), "r"(a2), "r"(a3), "r"(b0), "r"(b1));
}

__device__ __forceinline__ void cp_async16(uint32_t s, const void* g) {
    asm volatile("cp.async.cg.shared.global [%0], [%1], 16;" :: "r"(s), "l"(g));
}
__device__ __forceinline__ uint32_t smem_u32(const void* p) {
    return (uint32_t)__cvta_generic_to_shared(p);
}

// ---------------------------------------------------------------------------
// Elementwise tf32 pre-round (float4 grid-stride)
// ---------------------------------------------------------------------------
__global__ void round_tf32_kernel(const float* __restrict__ in,
                                  float* __restrict__ out, int n4)
{
    int i = blockIdx.x * blockDim.x + threadIdx.x;
    if (i < n4) {
        float4 v = reinterpret_cast<const float4*>(in)[i];
        v.x = tf32r(v.x); v.y = tf32r(v.y);
        v.z = tf32r(v.z); v.w = tf32r(v.w);
        reinterpret_cast<float4*>(out)[i] = v;
    }
}

// ---------------------------------------------------------------------------
// TF32 GEMM v4: block 128x128, 4 warps (2x2), warp tile 64x64, BK=32,
// 3-stage cp.async smem pipeline + REGISTER double-buffered fragments
// (prefetch kk+1 frags while issuing kk MMAs). Inputs tf32-pre-rounded.
// ---------------------------------------------------------------------------
#define AS_STRIDE 36
#define BS_STRIDE 136
#define A_TILE_F (128 * AS_STRIDE)          // 4608 floats
#define B_TILE_F (32 * BS_STRIDE)           // 4352 floats
#define BUF_F    (A_TILE_F + B_TILE_F)      // 8960 floats
#define SMEM_BYTES (3 * BUF_F * 4)          // 107520 bytes (3 stages)

template<bool ROUND_OUT>
__global__ __launch_bounds__(128, 2) void gemm_tf32_kernel(
    const float* __restrict__ A, const float* __restrict__ W,
    const float* __restrict__ bias, float* __restrict__ C,
    int M, int N, int K)
{
    extern __shared__ float sm[];

    const int tid  = threadIdx.x;
    const int lane = tid & 31;
    const int warp = tid >> 5;       // 0..3
    const int wm   = warp & 1;       // 0..1
    const int wn   = warp >> 1;      // 0..1
    const int mBase = blockIdx.y * 128;
    const int nBase = blockIdx.x * 128;
    const int g  = lane >> 2;        // 0..7
    const int t  = lane & 3;         // 0..3

    float acc[4][8][4];              // [mt][nt][frag]
    #pragma unroll
    for (int mt = 0; mt < 4; ++mt)
        #pragma unroll
        for (int nt = 0; nt < 8; ++nt)
            #pragma unroll
            for (int f = 0; f < 4; ++f) acc[mt][nt][f] = 0.0f;

    auto loadTile = [&](int buf, int k0) {
        float* As = sm + buf * BUF_F;
        float* Bs = As + A_TILE_F;
        #pragma unroll
        for (int j = 0; j < 8; ++j) {          // A: 128x32 = 1024 float4
            int idx = tid + j * 128;
            int r = idx >> 3, c4 = idx & 7;
            cp_async16(smem_u32(As + r * AS_STRIDE + c4 * 4),
                       &A[(size_t)(mBase + r) * K + k0 + c4 * 4]);
        }
        #pragma unroll
        for (int j = 0; j < 8; ++j) {          // B: 32x128 = 1024 float4
            int idx = tid + j * 128;
            int r = idx >> 5, c4 = idx & 31;
            cp_async16(smem_u32(Bs + r * BS_STRIDE + c4 * 4),
                       &W[(size_t)(k0 + r) * N + nBase + c4 * 4]);
        }
        asm volatile("cp.async.commit_group;");
    };

    // Register fragment buffers (double-buffered over kk)
    uint32_t af[2][4][4];
    uint32_t bf[2][8][2];

    const int aRow = wm * 64;        // warp's A row base
    const int bCol = wn * 64;        // warp's B col base

    auto loadFragsA = [&](int pb, const uint32_t* As, int kc) {
        #pragma unroll
        for (int mt = 0; mt < 4; ++mt) {
            int r = aRow + mt * 16 + g;
            af[pb][mt][0] = As[(r    ) * AS_STRIDE + kc + t    ];
            af[pb][mt][1] = As[(r + 8) * AS_STRIDE + kc + t    ];
            af[pb][mt][2] = As[(r    ) * AS_STRIDE + kc + t + 4];
            af[pb][mt][3] = As[(r + 8) * AS_STRIDE + kc + t + 4];
        }
    };
    auto loadFragsB = [&](int pb, const uint32_t* Bs, int kc) {
        #pragma unroll
        for (int nt = 0; nt < 8; ++nt) {
            int n = bCol + nt * 8 + g;
            bf[pb][nt][0] = Bs[(kc + t    ) * BS_STRIDE + n];
            bf[pb][nt][1] = Bs[(kc + t + 4) * BS_STRIDE + n];
        }
    };

    const int nIter = K / 32;        // 32
    loadTile(0, 0);
    loadTile(1, 32);

    for (int it = 0; it < nIter; ++it) {
        if (it + 1 < nIter) {
            asm volatile("cp.async.wait_group 1;");   // tile `it` resident
        } else {
            asm volatile("cp.async.wait_group 0;");
        }
        __syncthreads();   // tile `it` visible; everyone done with buf (it-1)%3

        if (it + 2 < nIter)
            loadTile((it + 2) % 3, (it + 2) * 32);    // overwrites buf (it-1)%3

        const uint32_t* As = reinterpret_cast<const uint32_t*>(sm + (it % 3) * BUF_F);
        const uint32_t* Bs = As + A_TILE_F;

        // prime kk=0 fragments
        loadFragsA(0, As, 0);
        loadFragsB(0, Bs, 0);

        #pragma unroll
        for (int kk = 0; kk < 4; ++kk) {
            const int cur = kk & 1;
            const int nxt = cur ^ 1;
            if (kk < 3) {                   // prefetch kk+1 while MMAs run
                loadFragsA(nxt, As, (kk + 1) * 8);
                loadFragsB(nxt, Bs, (kk + 1) * 8);
            }
            #pragma unroll
            for (int mt = 0; mt < 4; ++mt)
                #pragma unroll
                for (int nt = 0; nt < 8; ++nt)
                    mma_tf32(acc[mt][nt][0], acc[mt][nt][1],
                             acc[mt][nt][2], acc[mt][nt][3],
                             af[cur][mt][0], af[cur][mt][1],
                             af[cur][mt][2], af[cur][mt][3],
                             bf[cur][nt][0], bf[cur][nt][1]);
        }
    }

    // ---- epilogue: bias add, float2 stores ----
    #pragma unroll
    for (int mt = 0; mt < 4; ++mt) {
        int r0 = mBase + wm * 64 + mt * 16 + g;
        int r1 = r0 + 8;
        #pragma unroll
        for (int nt = 0; nt < 8; ++nt) {
            int col = nBase + wn * 64 + nt * 8 + t * 2;
            float2 bv = *reinterpret_cast<const float2*>(&bias[col]);
            float2 v0, v1;
            v0.x = acc[mt][nt][0] + bv.x;
            v0.y = acc[mt][nt][1] + bv.y;
            v1.x = acc[mt][nt][2] + bv.x;
            v1.y = acc[mt][nt][3] + bv.y;
            if (ROUND_OUT) {
                v0.x = tf32r(v0.x); v0.y = tf32r(v0.y);
                v1.x = tf32r(v1.x); v1.y = tf32r(v1.y);
            }
            *reinterpret_cast<float2*>(&C[(size_t)r0 * N + col]) = v0;
            *reinterpret_cast<float2*>(&C[(size_t)r1 * N + col]) = v1;
        }
    }
}

// ---------------------------------------------------------------------------
// Tensor-core FlashAttention (tf32, causal) — unchanged from R5.
// ---------------------------------------------------------------------------
#define QP_STRIDE 68
#define K_STRIDE  68
#define V_STRIDE  72
#define QP_F (128 * QP_STRIDE)
#define K_F  (64 * K_STRIDE)
#define V_F  (64 * V_STRIDE)
#define ATT_SMEM_BYTES ((QP_F + K_F + V_F) * 4)

__global__ __launch_bounds__(256, 2) void attention_tc_kernel(
    const float* __restrict__ qkv, float* __restrict__ attn)
{
    extern __shared__ float sm[];
    float* QP = sm;
    float* Ks = sm + QP_F;
    float* Vs = Ks + K_F;
    uint32_t* QPu = reinterpret_cast<uint32_t*>(QP);
    const uint32_t* Ksu = reinterpret_cast<const uint32_t*>(Ks);
    const uint32_t* Vsu = reinterpret_cast<const uint32_t*>(Vs);

    const int tid  = threadIdx.x;
    const int lane = tid & 31;
    const int warp = tid >> 5;
    const int g = lane >> 2;
    const int t = lane & 3;
    const int q0 = (7 - blockIdx.x) * 128;
    const int bh = blockIdx.y;
    const int b  = bh >> 4;
    const int h  = bh & 15;

    const float* qbase = qkv + (size_t)b * S_ * 3072 + h * DH_;
    const float* kbase = qbase + D_;
    const float* vbase = qbase + 2 * D_;

    #pragma unroll
    for (int i = 0; i < 8; ++i) {
        int idx = tid + i * 256;
        int r = idx >> 4, c4 = idx & 15;
        float4 v = *reinterpret_cast<const float4*>(
            qbase + (size_t)(q0 + r) * 3072 + c4 * 4);
        v.x *= 0.125f; v.y *= 0.125f; v.z *= 0.125f; v.w *= 0.125f;
        *reinterpret_cast<float4*>(QP + r * QP_STRIDE + c4 * 4) = v;
    }
    __syncthreads();

    const int rowA = warp * 16 + g;
    uint32_t qf[8][4];
    #pragma unroll
    for (int kk = 0; kk < 8; ++kk) {
        int c = kk * 8;
        qf[kk][0] = QPu[(rowA    ) * QP_STRIDE + c + t    ];
        qf[kk][1] = QPu[(rowA + 8) * QP_STRIDE + c + t    ];
        qf[kk][2] = QPu[(rowA    ) * QP_STRIDE + c + t + 4];
        qf[kk][3] = QPu[(rowA + 8) * QP_STRIDE + c + t + 4];
    }

    float of[8][4];
    #pragma unroll
    for (int nt = 0; nt < 8; ++nt)
        #pragma unroll
        for (int f = 0; f < 4; ++f) of[nt][f] = 0.0f;
    float m0 = -1e30f, m1 = -1e30f, l0 = 0.0f, l1 = 0.0f;

    const int nTiles = q0 / 64 + 2;
    for (int kt = 0; kt < nTiles; ++kt) {
        const int ks = kt * 64;
        __syncthreads();

        #pragma unroll
        for (int i = 0; i < 4; ++i) {
            int idx = tid + i * 256;
            int r = idx >> 4, c4 = idx & 15;
            *reinterpret_cast<float4*>(Ks + r * K_STRIDE + c4 * 4) =
                *reinterpret_cast<const float4*>(
                    kbase + (size_t)(ks + r) * 3072 + c4 * 4);
            *reinterpret_cast<float4*>(Vs + r * V_STRIDE + c4 * 4) =
                *reinterpret_cast<const float4*>(
                    vbase + (size_t)(ks + r) * 3072 + c4 * 4);
        }
        __syncthreads();

        float sv[8][4];
        #pragma unroll
        for (int nt = 0; nt < 8; ++nt) {
            sv[nt][0] = sv[nt][1] = sv[nt][2] = sv[nt][3] = 0.0f;
            #pragma unroll
            for (int kk = 0; kk < 8; ++kk) {
                uint32_t b0 = Ksu[(nt * 8 + g) * K_STRIDE + kk * 8 + t    ];
                uint32_t b1 = Ksu[(nt * 8 + g) * K_STRIDE + kk * 8 + t + 4];
                mma_tf32(sv[nt][0], sv[nt][1], sv[nt][2], sv[nt][3],
                         qf[kk][0], qf[kk][1], qf[kk][2], qf[kk][3], b0, b1);
            }
        }

        if (ks >= q0) {
            int r0 = q0 + rowA, r1 = r0 + 8;
            #pragma unroll
            for (int nt = 0; nt < 8; ++nt) {
                int c0 = ks + nt * 8 + 2 * t, c1 = c0 + 1;
                if (c0 > r0) sv[nt][0] = -1e30f;
                if (c1 > r0) sv[nt][1] = -1e30f;
                if (c0 > r1) sv[nt][2] = -1e30f;
                if (c1 > r1) sv[nt][3] = -1e30f;
            }
        }

        float rx0 = -1e30f, rx1 = -1e30f;
        #pragma unroll
        for (int nt = 0; nt < 8; ++nt) {
            rx0 = fmaxf(rx0, fmaxf(sv[nt][0], sv[nt][1]));
            rx1 = fmaxf(rx1, fmaxf(sv[nt][2], sv[nt][3]));
        }
        rx0 = fmaxf(rx0, __shfl_xor_sync(0xffffffffu, rx0, 1));
        rx0 = fmaxf(rx0, __shfl_xor_sync(0xffffffffu, rx0, 2));
        rx1 = fmaxf(rx1, __shfl_xor_sync(0xffffffffu, rx1, 1));
        rx1 = fmaxf(rx1, __shfl_xor_sync(0xffffffffu, rx1, 2));

        float mn0 = fmaxf(m0, rx0), mn1 = fmaxf(m1, rx1);
        float corr0 = __expf(m0 - mn0), corr1 = __expf(m1 - mn1);
        m0 = mn0; m1 = mn1;

        float ps0 = 0.0f, ps1 = 0.0f;
        #pragma unroll
        for (int nt = 0; nt < 8; ++nt) {
            float p0 = __expf(sv[nt][0] - m0);
            float p1 = __expf(sv[nt][1] - m0);
            float p2 = __expf(sv[nt][2] - m1);
            float p3 = __expf(sv[nt][3] - m1);
            ps0 += p0 + p1;
            ps1 += p2 + p3;
            uint2 w0; w0.x = f2tf32(p0); w0.y = f2tf32(p1);
            uint2 w1; w1.x = f2tf32(p2); w1.y = f2tf32(p3);
            *reinterpret_cast<uint2*>(QPu + (rowA    ) * QP_STRIDE + nt * 8 + 2 * t) = w0;
            *reinterpret_cast<uint2*>(QPu + (rowA + 8) * QP_STRIDE + nt * 8 + 2 * t) = w1;
        }
        ps0 += __shfl_xor_sync(0xffffffffu, ps0, 1);
        ps0 += __shfl_xor_sync(0xffffffffu, ps0, 2);
        ps1 += __shfl_xor_sync(0xffffffffu, ps1, 1);
        ps1 += __shfl_xor_sync(0xffffffffu, ps1, 2);
        l0 = l0 * corr0 + ps0;
        l1 = l1 * corr1 + ps1;

        #pragma unroll
        for (int nt = 0; nt < 8; ++nt) {
            of[nt][0] *= corr0; of[nt][1] *= corr0;
            of[nt][2] *= corr1; of[nt][3] *= corr1;
        }
        __syncwarp();

        #pragma unroll
        for (int kk = 0; kk < 8; ++kk) {
            uint32_t a0 = QPu[(rowA    ) * QP_STRIDE + kk * 8 + t    ];
            uint32_t a1 = QPu[(rowA + 8) * QP_STRIDE + kk * 8 + t    ];
            uint32_t a2 = QPu[(rowA    ) * QP_STRIDE + kk * 8 + t + 4];
            uint32_t a3 = QPu[(rowA + 8) * QP_STRIDE + kk * 8 + t + 4];
            #pragma unroll
            for (int nt = 0; nt < 8; ++nt) {
                uint32_t b0 = Vsu[(kk * 8 + t    ) * V_STRIDE + nt * 8 + g];
                uint32_t b1 = Vsu[(kk * 8 + t + 4) * V_STRIDE + nt * 8 + g];
                mma_tf32(of[nt][0], of[nt][1], of[nt][2], of[nt][3],
                         a0, a1, a2, a3, b0, b1);
            }
        }
    }

    const float inv0 = 1.0f / l0;
    const float inv1 = 1.0f / l1;
    const int r0 = q0 + rowA;
    float* obase = attn + ((size_t)b * S_ + r0) * D_ + h * DH_;
    #pragma unroll
    for (int nt = 0; nt < 8; ++nt) {
        int col = nt * 8 + 2 * t;
        float2 v0, v1;
        v0.x = tf32r(of[nt][0] * inv0); v0.y = tf32r(of[nt][1] * inv0);
        v1.x = tf32r(of[nt][2] * inv1); v1.y = tf32r(of[nt][3] * inv1);
        *reinterpret_cast<float2*>(obase + col) = v0;
        *reinterpret_cast<float2*>(obase + 8 * (size_t)D_ + col) = v1;
    }
}

// ---------------------------------------------------------------------------
// Launch
// ---------------------------------------------------------------------------
extern "C" void kernel_launch(void* const* d_in, const int* in_sizes, int n_in,
                              void* d_out, int out_size)
{
    (void)in_sizes; (void)n_in; (void)out_size;
    const float* x     = (const float*)d_in[0];
    const float* W_qkv = (const float*)d_in[1];
    const float* b_qkv = (const float*)d_in[2];
    const float* W_out = (const float*)d_in[3];
    const float* b_out = (const float*)d_in[4];
    float* out = (float*)d_out;

    float *qkv, *attn, *xr, *wqkvr, *woutr;
    cudaGetSymbolAddress((void**)&qkv,   g_qkv);
    cudaGetSymbolAddress((void**)&attn,  g_attn);
    cudaGetSymbolAddress((void**)&xr,    g_x);
    cudaGetSymbolAddress((void**)&wqkvr, g_wqkv);
    cudaGetSymbolAddress((void**)&woutr, g_wout);

    cudaFuncSetAttribute(gemm_tf32_kernel<true>,
                         cudaFuncAttributeMaxDynamicSharedMemorySize, SMEM_BYTES);
    cudaFuncSetAttribute(gemm_tf32_kernel<false>,
                         cudaFuncAttributeMaxDynamicSharedMemorySize, SMEM_BYTES);
    cudaFuncSetAttribute(attention_tc_kernel,
                         cudaFuncAttributeMaxDynamicSharedMemorySize, ATT_SMEM_BYTES);

    // 0) Pre-round inputs to tf32-representable fp32
    {
        int nx = B_ * S_ * D_ / 4;
        round_tf32_kernel<<<(nx + 255) / 256, 256>>>(x, xr, nx);
        int nw = D_ * 3 * D_ / 4;
        round_tf32_kernel<<<(nw + 255) / 256, 256>>>(W_qkv, wqkvr, nw);
        int no = D_ * D_ / 4;
        round_tf32_kernel<<<(no + 255) / 256, 256>>>(W_out, woutr, no);
    }

    // 1) QKV projection -> g_qkv (tf32-rounded output)
    {
        dim3 grid(3 * D_ / 128, (B_ * S_) / 128);
        gemm_tf32_kernel<true><<<grid, 128, SMEM_BYTES>>>(xr, wqkvr, b_qkv, qkv,
                                                          B_ * S_, 3 * D_, D_);
    }

    // 2) Tensor-core causal flash attention -> g_attn (tf32-rounded)
    {
        dim3 grid(S_ / 128, B_ * H_);
        attention_tc_kernel<<<grid, 256, ATT_SMEM_BYTES>>>(qkv, attn);
    }

    // 3) Output projection -> d_out (full fp32 output)
    {
        dim3 grid(D_ / 128, (B_ * S_) / 128);
        gemm_tf32_kernel<false><<<grid, 128, SMEM_BYTES>>>(attn, woutr, b_out, out,
                                                           B_ * S_, D_, D_);
    }
}